// round 6
// baseline (speedup 1.0000x reference)
#include <cuda_runtime.h>
#include <cuda_bf16.h>
#include <math.h>
#include <stdint.h>

// ---------------------------------------------------------------------------
// Problem constants
// ---------------------------------------------------------------------------
#define NB      2
#define T_SEQ   2048
#define NT      (NB * T_SEQ)        // 4096 tokens
#define DM      1024
#define H_NUM   16
#define HD      64
#define DFF     4096
#define QKV_N   (3 * DM)            // 3072
#define LN_EPS  1e-3f
#define QSCALE  0.18033688011112042f   // 0.125 * log2(e)

// ---------------------------------------------------------------------------
// Scratch
// ---------------------------------------------------------------------------
__device__ float g_ctx[NT * DM];
__device__ float g_h1 [NT * DM];
__device__ float g_tmp[NT * DM];
__device__ __nv_bfloat16 g_ahi[NT * DM];
__device__ __nv_bfloat16 g_alo[NT * DM];
__device__ __nv_bfloat16 g_bhi[4 * 1024 * 1024];
__device__ __nv_bfloat16 g_blo[4 * 1024 * 1024];
__device__ __nv_bfloat16 g_ffhi[NT * DFF];
__device__ __nv_bfloat16 g_fflo[NT * DFF];
// attention-native QKV (bf16, layout [token][h*64+d])
__device__ __nv_bfloat16 g_qh[NT * DM];
__device__ __nv_bfloat16 g_ql[NT * DM];
__device__ __nv_bfloat16 g_kh[NT * DM];
__device__ __nv_bfloat16 g_kl[NT * DM];
__device__ __nv_bfloat16 g_vb[NT * DM];

// ---------------------------------------------------------------------------
// Helpers
// ---------------------------------------------------------------------------
__device__ __forceinline__ void split_pack2(float x, float y,
                                            uint32_t& hi, uint32_t& lo)
{
    __nv_bfloat16 hx = __float2bfloat16(x);
    __nv_bfloat16 hy = __float2bfloat16(y);
    __nv_bfloat16 lx = __float2bfloat16(x - __bfloat162float(hx));
    __nv_bfloat16 ly = __float2bfloat16(y - __bfloat162float(hy));
    hi = (uint32_t)__bfloat16_as_ushort(hx) |
         ((uint32_t)__bfloat16_as_ushort(hy) << 16);
    lo = (uint32_t)__bfloat16_as_ushort(lx) |
         ((uint32_t)__bfloat16_as_ushort(ly) << 16);
}

__device__ __forceinline__ uint32_t pack_bf16(float x, float y)
{
    return (uint32_t)__bfloat16_as_ushort(__float2bfloat16(x)) |
           ((uint32_t)__bfloat16_as_ushort(__float2bfloat16(y)) << 16);
}

#define MMA_BF16(d, a, b)                                                   \
    asm volatile(                                                           \
        "mma.sync.aligned.m16n8k16.row.col.f32.bf16.bf16.f32 "              \
        "{%0,%1,%2,%3}, {%4,%5,%6,%7}, {%8,%9}, {%0,%1,%2,%3};"             \
        : "+f"(d[0]), "+f"(d[1]), "+f"(d[2]), "+f"(d[3])                    \
        : "r"(a[0]), "r"(a[1]), "r"(a[2]), "r"(a[3]), "r"(b[0]), "r"(b[1]))

#define LDSM_X4(R, addr)                                                    \
    asm volatile("ldmatrix.sync.aligned.m8n8.x4.shared.b16 "                \
                 "{%0,%1,%2,%3}, [%4];"                                     \
                 : "=r"(R[0]), "=r"(R[1]), "=r"(R[2]), "=r"(R[3])           \
                 : "r"(addr))

#define LDSM_X4_T(R, addr)                                                  \
    asm volatile("ldmatrix.sync.aligned.m8n8.x4.trans.shared.b16 "          \
                 "{%0,%1,%2,%3}, [%4];"                                     \
                 : "=r"(R[0]), "=r"(R[1]), "=r"(R[2]), "=r"(R[3])           \
                 : "r"(addr))

__device__ __forceinline__ void cp16(uint32_t dst, const void* src)
{
    asm volatile("cp.async.cg.shared.global [%0], [%1], 16;"
                 :: "r"(dst), "l"(src));
}

// ---------------------------------------------------------------------------
// Conversion kernels
// ---------------------------------------------------------------------------
__global__ void convert_split_kernel(const float* __restrict__ in,
                                     __nv_bfloat16* __restrict__ hi,
                                     __nv_bfloat16* __restrict__ lo,
                                     int npairs)
{
    int i = blockIdx.x * blockDim.x + threadIdx.x;
    if (i >= npairs) return;
    float2 v = ((const float2*)in)[i];
    uint32_t h, l;
    split_pack2(v.x, v.y, h, l);
    ((uint32_t*)hi)[i] = h;
    ((uint32_t*)lo)[i] = l;
}

// W [Kd][Nd] fp32 -> Wt hi/lo bf16 [Nd][Kd].
// qkv_perm: dest row for src col n is (n%3)*1024 + n/3.
__global__ void convert_wT_kernel(const float* __restrict__ W,
                                  __nv_bfloat16* __restrict__ hi,
                                  __nv_bfloat16* __restrict__ lo,
                                  int Kd, int Nd, int qkv_perm)
{
    __shared__ float t[32][33];
    const int tx = threadIdx.x, ty = threadIdx.y;
    const int n0 = blockIdx.x * 32, k0 = blockIdx.y * 32;
    #pragma unroll
    for (int r = ty; r < 32; r += 8)
        t[r][tx] = W[(size_t)(k0 + r) * Nd + n0 + tx];
    __syncthreads();
    #pragma unroll
    for (int r = ty; r < 32; r += 8) {
        float v = t[tx][r];
        int n = n0 + r;
        int drow = qkv_perm ? ((n % 3) * 1024 + n / 3) : n;
        __nv_bfloat16 h = __float2bfloat16(v);
        hi[(size_t)drow * Kd + k0 + tx] = h;
        lo[(size_t)drow * Kd + k0 + tx] =
            __float2bfloat16(v - __bfloat162float(h));
    }
}

// ---------------------------------------------------------------------------
// Tensor-core GEMM, bf16x3 split, 3-stage cp.async pipeline + ldmatrix.
// One __syncthreads per k32 iteration. 1 CTA/SM (120 KB smem).
// ---------------------------------------------------------------------------
#define ROWB   80
#define ABUF   10240
#define OFF_AH 0
#define OFF_AL 30720
#define OFF_BH 61440
#define OFF_BL 92160
#define GEMM_SMEM_BYTES 122880

__global__ __launch_bounds__(256)
void gemm_mma_kernel(const __nv_bfloat16* __restrict__ Ahi,
                     const __nv_bfloat16* __restrict__ Alo,
                     const __nv_bfloat16* __restrict__ Bhi,
                     const __nv_bfloat16* __restrict__ Blo,
                     const float* __restrict__ bias,
                     float* __restrict__ Cf,
                     __nv_bfloat16* __restrict__ Chi,
                     __nv_bfloat16* __restrict__ Clo,
                     __nv_bfloat16* __restrict__ Qh,
                     __nv_bfloat16* __restrict__ Ql,
                     __nv_bfloat16* __restrict__ Kh,
                     __nv_bfloat16* __restrict__ Kl,
                     __nv_bfloat16* __restrict__ Vb,
                     int N, int K, int relu)
{
    extern __shared__ char smem[];
    const uint32_t sb = (uint32_t)__cvta_generic_to_shared(smem);

    const int tid  = threadIdx.x;
    const int warp = tid >> 5;
    const int lane = tid & 31;
    const int m0   = blockIdx.y * 128;
    const int n0   = blockIdx.x * 128;
    const int wm   = (warp >> 1) * 32;
    const int wn   = (warp & 1) * 64;
    const int tg   = lane & 3;
    const int grp  = lane >> 2;

    float acc[2][8][4];
    #pragma unroll
    for (int i = 0; i < 2; i++)
        #pragma unroll
        for (int j = 0; j < 8; j++)
            #pragma unroll
            for (int q = 0; q < 4; q++) acc[i][j][q] = 0.0f;

    auto issueTile = [&](int k0, int buf) {
        const uint32_t bo = buf * ABUF;
        #pragma unroll
        for (int t = 0; t < 2; t++) {
            int q   = tid + t * 256;
            int row = q >> 2, ch = q & 3;
            uint32_t so = bo + row * ROWB + ch * 16;
            size_t ao  = (size_t)(m0 + row) * K + k0 + ch * 8;
            size_t bo2 = (size_t)(n0 + row) * K + k0 + ch * 8;
            cp16(sb + OFF_AH + so, Ahi + ao);
            cp16(sb + OFF_AL + so, Alo + ao);
            cp16(sb + OFF_BH + so, Bhi + bo2);
            cp16(sb + OFF_BL + so, Blo + bo2);
        }
    };

    auto computeTile = [&](int buf) {
        const uint32_t bo = buf * ABUF;
        const int rr = lane & 15;
        #pragma unroll
        for (int kc = 0; kc < 2; kc++) {
            const uint32_t ko = kc * 32 + ((lane >> 4) << 4);
            uint32_t ah[2][4], al[2][4];
            #pragma unroll
            for (int i = 0; i < 2; i++) {
                uint32_t ad = sb + bo + (wm + i * 16 + rr) * ROWB + ko;
                LDSM_X4(ah[i], ad + OFF_AH);
                LDSM_X4(al[i], ad + OFF_AL);
            }
            #pragma unroll
            for (int jj = 0; jj < 4; jj++) {
                uint32_t bd = sb + bo + (wn + jj * 16 + rr) * ROWB + ko;
                uint32_t bh[4], bl[4];
                LDSM_X4(bh, bd + OFF_BH);
                LDSM_X4(bl, bd + OFF_BL);
                uint32_t bh0[2] = { bh[0], bh[2] }, bh1[2] = { bh[1], bh[3] };
                uint32_t bl0[2] = { bl[0], bl[2] }, bl1[2] = { bl[1], bl[3] };
                #pragma unroll
                for (int i = 0; i < 2; i++) {
                    MMA_BF16(acc[i][2*jj],   ah[i], bh0);
                    MMA_BF16(acc[i][2*jj],   ah[i], bl0);
                    MMA_BF16(acc[i][2*jj],   al[i], bh0);
                    MMA_BF16(acc[i][2*jj+1], ah[i], bh1);
                    MMA_BF16(acc[i][2*jj+1], ah[i], bl1);
                    MMA_BF16(acc[i][2*jj+1], al[i], bh1);
                }
            }
        }
    };

    const int nIter = K >> 5;   // always >= 32
    issueTile(0, 0);
    asm volatile("cp.async.commit_group;");
    issueTile(32, 1);
    asm volatile("cp.async.commit_group;");

    for (int it = 0; it < nIter; it++) {
        const int buf = it % 3;
        asm volatile("cp.async.wait_group 1;");
        __syncthreads();
        if (it + 2 < nIter) {
            issueTile((it + 2) << 5, (it + 2) % 3);
            asm volatile("cp.async.commit_group;");
        }
        computeTile(buf);
    }

    // ---- epilogue ----
    #pragma unroll
    for (int i = 0; i < 2; i++) {
        int r = m0 + wm + i * 16 + grp;
        #pragma unroll
        for (int j = 0; j < 8; j++) {
            int c = n0 + wn + j * 8 + tg * 2;
            if (Qh) {
                int comp = c >> 10, cd = c & 1023;
                float b0 = bias[cd * 3 + comp], b1 = bias[(cd + 1) * 3 + comp];
                float v0 = acc[i][j][0] + b0, v1 = acc[i][j][1] + b1;
                float v2 = acc[i][j][2] + b0, v3 = acc[i][j][3] + b1;
                size_t o0 = (size_t)r * DM + cd;
                size_t o1 = (size_t)(r + 8) * DM + cd;
                uint32_t h, l;
                if (comp == 0) {
                    split_pack2(v0 * QSCALE, v1 * QSCALE, h, l);
                    *(uint32_t*)&Qh[o0] = h; *(uint32_t*)&Ql[o0] = l;
                    split_pack2(v2 * QSCALE, v3 * QSCALE, h, l);
                    *(uint32_t*)&Qh[o1] = h; *(uint32_t*)&Ql[o1] = l;
                } else if (comp == 1) {
                    split_pack2(v0, v1, h, l);
                    *(uint32_t*)&Kh[o0] = h; *(uint32_t*)&Kl[o0] = l;
                    split_pack2(v2, v3, h, l);
                    *(uint32_t*)&Kh[o1] = h; *(uint32_t*)&Kl[o1] = l;
                } else {
                    *(uint32_t*)&Vb[o0] = pack_bf16(v0, v1);
                    *(uint32_t*)&Vb[o1] = pack_bf16(v2, v3);
                }
            } else {
                float b0 = bias[c], b1 = bias[c + 1];
                float v0 = acc[i][j][0] + b0, v1 = acc[i][j][1] + b1;
                float v2 = acc[i][j][2] + b0, v3 = acc[i][j][3] + b1;
                if (relu) {
                    v0 = fmaxf(v0, 0.0f); v1 = fmaxf(v1, 0.0f);
                    v2 = fmaxf(v2, 0.0f); v3 = fmaxf(v3, 0.0f);
                }
                if (Cf) {
                    *(float2*)&Cf[(size_t)r * N + c]       = make_float2(v0, v1);
                    *(float2*)&Cf[(size_t)(r + 8) * N + c] = make_float2(v2, v3);
                } else {
                    uint32_t h, l;
                    split_pack2(v0, v1, h, l);
                    *(uint32_t*)&Chi[(size_t)r * N + c] = h;
                    *(uint32_t*)&Clo[(size_t)r * N + c] = l;
                    split_pack2(v2, v3, h, l);
                    *(uint32_t*)&Chi[(size_t)(r + 8) * N + c] = h;
                    *(uint32_t*)&Clo[(size_t)(r + 8) * N + c] = l;
                }
            }
        }
    }
}

// ---------------------------------------------------------------------------
// Tensor-core flash attention, 3-stage KV pipeline, exp2 softmax.
// Grid (T/128, H, N), 256 threads, 2 CTAs/SM. Q pre-scaled by 0.125*log2e.
// ---------------------------------------------------------------------------
#define ATT_SROW 144
#define ATT_KBUF 27648          // per buf: Kh 9216 | Kl 9216 | V 9216
#define ATT_SMEM 82944          // 3 buffers

__global__ __launch_bounds__(256, 2)
void attention_mma_kernel(const __nv_bfloat16* __restrict__ Qh,
                          const __nv_bfloat16* __restrict__ Ql,
                          const __nv_bfloat16* __restrict__ Kh,
                          const __nv_bfloat16* __restrict__ Kl,
                          const __nv_bfloat16* __restrict__ Vb,
                          float* __restrict__ ctx)
{
    extern __shared__ char smem[];
    const uint32_t sb = (uint32_t)__cvta_generic_to_shared(smem);

    const int tid  = threadIdx.x;
    const int warp = tid >> 5;
    const int lane = tid & 31;
    const int tg   = lane & 3;
    const int grp  = lane >> 2;
    const int wm   = warp * 16;
    const int rr   = lane & 15;
    const int kb   = (lane >> 4) << 4;

    const int q0 = blockIdx.x * 128;
    const int h  = blockIdx.y;
    const int n  = blockIdx.z;
    const int h64 = h * HD;
    const size_t row_base = (size_t)n * T_SEQ;

    // ---- stage Q (hi at 0, lo at 18432), extract resident fragments ----
    #pragma unroll
    for (int t = 0; t < 4; t++) {
        int u = tid + t * 256;
        int row = u >> 3, ch = u & 7;
        size_t g = (size_t)(row_base + q0 + row) * DM + h64 + ch * 8;
        uint32_t so = row * ATT_SROW + ch * 16;
        cp16(sb + so, Qh + g);
        cp16(sb + 18432 + so, Ql + g);
    }
    asm volatile("cp.async.commit_group;");
    asm volatile("cp.async.wait_group 0;");
    __syncthreads();

    uint32_t qfh[4][4], qfl[4][4];
    #pragma unroll
    for (int kc = 0; kc < 4; kc++) {
        uint32_t ad = sb + (wm + rr) * ATT_SROW + kc * 32 + kb;
        LDSM_X4(qfh[kc], ad);
        LDSM_X4(qfl[kc], ad + 18432);
    }
    __syncthreads();   // Q consumed before KV buffers overwrite the region

    auto issueKV = [&](int kt, int buf) {
        uint32_t bo = sb + buf * ATT_KBUF;
        int kv0 = kt * 64;
        #pragma unroll
        for (int t = 0; t < 2; t++) {
            int u = tid + t * 256;
            int row = u >> 3, ch = u & 7;
            size_t g = (size_t)(row_base + kv0 + row) * DM + h64 + ch * 8;
            uint32_t so = row * ATT_SROW + ch * 16;
            cp16(bo + so,         Kh + g);
            cp16(bo + 9216 + so,  Kl + g);
            cp16(bo + 18432 + so, Vb + g);
        }
    };

    float o[8][4];
    #pragma unroll
    for (int j = 0; j < 8; j++)
        #pragma unroll
        for (int q = 0; q < 4; q++) o[j][q] = 0.0f;
    float m0 = -1e30f, m1 = -1e30f, l0 = 0.0f, l1 = 0.0f;

    const int nTiles = T_SEQ / 64;
    issueKV(0, 0);
    asm volatile("cp.async.commit_group;");
    issueKV(1, 1);
    asm volatile("cp.async.commit_group;");

    for (int kt = 0; kt < nTiles; kt++) {
        const int buf = kt % 3;
        asm volatile("cp.async.wait_group 1;");
        __syncthreads();
        if (kt + 2 < nTiles) {
            issueKV(kt + 2, (kt + 2) % 3);
            asm volatile("cp.async.commit_group;");
        }

        const uint32_t bo = sb + buf * ATT_KBUF;

        // ---- S = Q @ K^T (log2-domain logits) ----
        float s[8][4];
        #pragma unroll
        for (int j = 0; j < 8; j++)
            #pragma unroll
            for (int q = 0; q < 4; q++) s[j][q] = 0.0f;
        #pragma unroll
        for (int jj = 0; jj < 4; jj++) {
            #pragma unroll
            for (int kc = 0; kc < 4; kc++) {
                uint32_t ad = bo + (jj * 16 + rr) * ATT_SROW + kc * 32 + kb;
                uint32_t bh[4], bl[4];
                LDSM_X4(bh, ad);
                LDSM_X4(bl, ad + 9216);
                uint32_t bh0[2] = { bh[0], bh[2] }, bh1[2] = { bh[1], bh[3] };
                uint32_t bl0[2] = { bl[0], bl[2] }, bl1[2] = { bl[1], bl[3] };
                MMA_BF16(s[2*jj],   qfh[kc], bh0);
                MMA_BF16(s[2*jj],   qfh[kc], bl0);
                MMA_BF16(s[2*jj],   qfl[kc], bh0);
                MMA_BF16(s[2*jj+1], qfh[kc], bh1);
                MMA_BF16(s[2*jj+1], qfh[kc], bl1);
                MMA_BF16(s[2*jj+1], qfl[kc], bh1);
            }
        }

        // ---- online softmax (base-2) ----
        float mx0 = -1e30f, mx1 = -1e30f;
        #pragma unroll
        for (int j = 0; j < 8; j++) {
            mx0 = fmaxf(mx0, fmaxf(s[j][0], s[j][1]));
            mx1 = fmaxf(mx1, fmaxf(s[j][2], s[j][3]));
        }
        mx0 = fmaxf(mx0, __shfl_xor_sync(0xffffffff, mx0, 1));
        mx0 = fmaxf(mx0, __shfl_xor_sync(0xffffffff, mx0, 2));
        mx1 = fmaxf(mx1, __shfl_xor_sync(0xffffffff, mx1, 1));
        mx1 = fmaxf(mx1, __shfl_xor_sync(0xffffffff, mx1, 2));
        float mn0 = fmaxf(m0, mx0), mn1 = fmaxf(m1, mx1);
        float al0 = exp2f(m0 - mn0), al1 = exp2f(m1 - mn1);
        float sum0 = 0.0f, sum1 = 0.0f;
        #pragma unroll
        for (int j = 0; j < 8; j++) {
            s[j][0] = exp2f(s[j][0] - mn0);
            s[j][1] = exp2f(s[j][1] - mn0);
            s[j][2] = exp2f(s[j][2] - mn1);
            s[j][3] = exp2f(s[j][3] - mn1);
            sum0 += s[j][0] + s[j][1];
            sum1 += s[j][2] + s[j][3];
        }
        sum0 += __shfl_xor_sync(0xffffffff, sum0, 1);
        sum0 += __shfl_xor_sync(0xffffffff, sum0, 2);
        sum1 += __shfl_xor_sync(0xffffffff, sum1, 1);
        sum1 += __shfl_xor_sync(0xffffffff, sum1, 2);
        m0 = mn0; m1 = mn1;
        l0 = l0 * al0 + sum0;
        l1 = l1 * al1 + sum1;
        #pragma unroll
        for (int j = 0; j < 8; j++) {
            o[j][0] *= al0; o[j][1] *= al0;
            o[j][2] *= al1; o[j][3] *= al1;
        }

        // ---- P fragments + PV (V via ldmatrix.trans) ----
        uint32_t ap[4][4];
        #pragma unroll
        for (int kc = 0; kc < 4; kc++) {
            ap[kc][0] = pack_bf16(s[2*kc][0],   s[2*kc][1]);
            ap[kc][1] = pack_bf16(s[2*kc][2],   s[2*kc][3]);
            ap[kc][2] = pack_bf16(s[2*kc+1][0], s[2*kc+1][1]);
            ap[kc][3] = pack_bf16(s[2*kc+1][2], s[2*kc+1][3]);
        }
        const uint32_t vrow = ((lane >> 4) << 3) + (lane & 7);
        const uint32_t vcol = ((lane >> 3) & 1) << 3;
        #pragma unroll
        for (int jd = 0; jd < 4; jd++) {
            #pragma unroll
            for (int kc = 0; kc < 4; kc++) {
                uint32_t va = bo + 18432 + (kc * 16 + vrow) * ATT_SROW
                            + (jd * 16 + vcol) * 2;
                uint32_t vr[4];
                LDSM_X4_T(vr, va);
                uint32_t vg0[2] = { vr[0], vr[2] }, vg1[2] = { vr[1], vr[3] };
                MMA_BF16(o[2*jd],   ap[kc], vg0);
                MMA_BF16(o[2*jd+1], ap[kc], vg1);
            }
        }
    }

    // ---- epilogue ----
    float inv0 = 1.0f / l0, inv1 = 1.0f / l1;
    size_t r0 = (row_base + q0 + wm + grp) * (size_t)DM + h64;
    size_t r1 = r0 + 8 * (size_t)DM;
    #pragma unroll
    for (int j = 0; j < 8; j++) {
        int c = j * 8 + tg * 2;
        *(float2*)&ctx[r0 + c] = make_float2(o[j][0] * inv0, o[j][1] * inv0);
        *(float2*)&ctx[r1 + c] = make_float2(o[j][2] * inv1, o[j][3] * inv1);
    }
}

// ---------------------------------------------------------------------------
// out = LayerNorm(a + b) * gamma + beta; optional hi/lo bf16 side outputs.
// ---------------------------------------------------------------------------
__global__ void add_ln_kernel(const float* __restrict__ a,
                              const float* __restrict__ b,
                              const float* __restrict__ gamma,
                              const float* __restrict__ beta,
                              float* __restrict__ out,
                              __nv_bfloat16* __restrict__ ohi,
                              __nv_bfloat16* __restrict__ olo)
{
    __shared__ float red[256];
    const int row = blockIdx.x;
    const int tid = threadIdx.x;
    const size_t base = (size_t)row * DM;

    float v[4];
    float s = 0.0f;
    #pragma unroll
    for (int i = 0; i < 4; i++) {
        int c = tid + 256 * i;
        v[i] = a[base + c] + b[base + c];
        s += v[i];
    }
    red[tid] = s;
    __syncthreads();
    #pragma unroll
    for (int off = 128; off > 0; off >>= 1) {
        if (tid < off) red[tid] += red[tid + off];
        __syncthreads();
    }
    const float mu = red[0] * (1.0f / DM);
    __syncthreads();

    float s2 = 0.0f;
    #pragma unroll
    for (int i = 0; i < 4; i++) {
        float d = v[i] - mu;
        s2 += d * d;
    }
    red[tid] = s2;
    __syncthreads();
    #pragma unroll
    for (int off = 128; off > 0; off >>= 1) {
        if (tid < off) red[tid] += red[tid + off];
        __syncthreads();
    }
    const float rs = rsqrtf(red[0] * (1.0f / DM) + LN_EPS);

    #pragma unroll
    for (int i = 0; i < 4; i++) {
        int c = tid + 256 * i;
        float y = (v[i] - mu) * rs * gamma[c] + beta[c];
        out[base + c] = y;
        if (ohi) {
            __nv_bfloat16 hb = __float2bfloat16(y);
            ohi[base + c] = hb;
            olo[base + c] = __float2bfloat16(y - __bfloat162float(hb));
        }
    }
}

// ---------------------------------------------------------------------------
// Launch
// ---------------------------------------------------------------------------
extern "C" void kernel_launch(void* const* d_in, const int* in_sizes, int n_in,
                              void* d_out, int out_size)
{
    const float* x     = (const float*)d_in[0];
    /* mask = d_in[1] : query-axis mask -> softmax shift -> no-op */
    const float* w_qkv = (const float*)d_in[2];
    const float* b_qkv = (const float*)d_in[3];
    const float* w_ff  = (const float*)d_in[4];
    const float* b_ff  = (const float*)d_in[5];
    const float* w_out = (const float*)d_in[6];
    const float* b_out = (const float*)d_in[7];
    const float* ln1_g = (const float*)d_in[8];
    const float* ln1_b = (const float*)d_in[9];
    const float* ln2_g = (const float*)d_in[10];
    const float* ln2_b = (const float*)d_in[11];
    float* out = (float*)d_out;

    float *ctx, *h1, *tmp;
    __nv_bfloat16 *ahi, *alo, *bhi, *blo, *ffhi, *fflo;
    __nv_bfloat16 *qh, *ql, *kh, *kl, *vb;
    cudaGetSymbolAddress((void**)&ctx,  g_ctx);
    cudaGetSymbolAddress((void**)&h1,   g_h1);
    cudaGetSymbolAddress((void**)&tmp,  g_tmp);
    cudaGetSymbolAddress((void**)&ahi,  g_ahi);
    cudaGetSymbolAddress((void**)&alo,  g_alo);
    cudaGetSymbolAddress((void**)&bhi,  g_bhi);
    cudaGetSymbolAddress((void**)&blo,  g_blo);
    cudaGetSymbolAddress((void**)&ffhi, g_ffhi);
    cudaGetSymbolAddress((void**)&fflo, g_fflo);
    cudaGetSymbolAddress((void**)&qh,   g_qh);
    cudaGetSymbolAddress((void**)&ql,   g_ql);
    cudaGetSymbolAddress((void**)&kh,   g_kh);
    cudaGetSymbolAddress((void**)&kl,   g_kl);
    cudaGetSymbolAddress((void**)&vb,   g_vb);

    static int smem_set = 0;
    if (!smem_set) {
        cudaFuncSetAttribute(gemm_mma_kernel,
                             cudaFuncAttributeMaxDynamicSharedMemorySize,
                             GEMM_SMEM_BYTES);
        cudaFuncSetAttribute(attention_mma_kernel,
                             cudaFuncAttributeMaxDynamicSharedMemorySize,
                             ATT_SMEM);
        smem_set = 1;
    }

    // 0) Convert x -> hi/lo; w_qkv -> transposed+permuted hi/lo
    convert_split_kernel<<<(NT * DM / 2 + 255) / 256, 256>>>(x, ahi, alo, NT * DM / 2);
    convert_wT_kernel<<<dim3(QKV_N / 32, DM / 32), dim3(32, 8)>>>(w_qkv, bhi, blo, DM, QKV_N, 1);

    // 1) QKV projection -> attention-native bf16 Q/K/V (Q pre-scaled)
    gemm_mma_kernel<<<dim3(QKV_N / 128, NT / 128), 256, GEMM_SMEM_BYTES>>>(
        ahi, alo, bhi, blo, b_qkv, nullptr, nullptr, nullptr,
        qh, ql, kh, kl, vb, QKV_N, DM, 0);

    // 2) Attention
    attention_mma_kernel<<<dim3(T_SEQ / 128, H_NUM, NB), 256, ATT_SMEM>>>(
        qh, ql, kh, kl, vb, ctx);

    // 3) h1 = LN(x + ctx), emit h1 hi/lo
    add_ln_kernel<<<NT, 256>>>(x, ctx, ln1_g, ln1_b, h1, ahi, alo);

    // 4) ff = relu(h1 @ w_ff + b_ff) -> hi/lo bf16
    convert_wT_kernel<<<dim3(DFF / 32, DM / 32), dim3(32, 8)>>>(w_ff, bhi, blo, DM, DFF, 0);
    gemm_mma_kernel<<<dim3(DFF / 128, NT / 128), 256, GEMM_SMEM_BYTES>>>(
        ahi, alo, bhi, blo, b_ff, nullptr, ffhi, fflo,
        nullptr, nullptr, nullptr, nullptr, nullptr, DFF, DM, 1);

    // 5) tmp = ff @ w_out + b_out -> fp32
    convert_wT_kernel<<<dim3(DM / 32, DFF / 32), dim3(32, 8)>>>(w_out, bhi, blo, DFF, DM, 0);
    gemm_mma_kernel<<<dim3(DM / 128, NT / 128), 256, GEMM_SMEM_BYTES>>>(
        ffhi, fflo, bhi, blo, b_out, tmp, nullptr, nullptr,
        nullptr, nullptr, nullptr, nullptr, nullptr, DM, DFF, 0);

    // 6) out = LN(h1 + tmp)
    add_ln_kernel<<<NT, 256>>>(h1, tmp, ln2_g, ln2_b, out, nullptr, nullptr);
}

// round 8
// speedup vs baseline: 1.1748x; 1.1748x over previous
#include <cuda_runtime.h>
#include <cuda_bf16.h>
#include <math.h>
#include <stdint.h>

// ---------------------------------------------------------------------------
// Problem constants
// ---------------------------------------------------------------------------
#define NB      2
#define T_SEQ   2048
#define NT      (NB * T_SEQ)        // 4096 tokens
#define DM      1024
#define H_NUM   16
#define HD      64
#define DFF     4096
#define QKV_N   (3 * DM)            // 3072
#define LN_EPS  1e-3f
#define QSCALE  0.18033688011112042f   // 0.125 * log2(e)

// ---------------------------------------------------------------------------
// Scratch
// ---------------------------------------------------------------------------
__device__ float g_ctx[NT * DM];
__device__ float g_h1 [NT * DM];
__device__ float g_tmp[NT * DM];
__device__ __nv_bfloat16 g_ahi[NT * DM];
__device__ __nv_bfloat16 g_alo[NT * DM];
__device__ __nv_bfloat16 g_bhi[4 * 1024 * 1024];
__device__ __nv_bfloat16 g_blo[4 * 1024 * 1024];
__device__ __nv_bfloat16 g_ffhi[NT * DFF];
__device__ __nv_bfloat16 g_fflo[NT * DFF];
// attention-native QKV (bf16, layout [token][h*64+d])
__device__ __nv_bfloat16 g_qh[NT * DM];
__device__ __nv_bfloat16 g_ql[NT * DM];
__device__ __nv_bfloat16 g_kh[NT * DM];
__device__ __nv_bfloat16 g_kl[NT * DM];
__device__ __nv_bfloat16 g_vb[NT * DM];

// ---------------------------------------------------------------------------
// Helpers
// ---------------------------------------------------------------------------
__device__ __forceinline__ void split_pack2(float x, float y,
                                            uint32_t& hi, uint32_t& lo)
{
    __nv_bfloat16 hx = __float2bfloat16(x);
    __nv_bfloat16 hy = __float2bfloat16(y);
    __nv_bfloat16 lx = __float2bfloat16(x - __bfloat162float(hx));
    __nv_bfloat16 ly = __float2bfloat16(y - __bfloat162float(hy));
    hi = (uint32_t)__bfloat16_as_ushort(hx) |
         ((uint32_t)__bfloat16_as_ushort(hy) << 16);
    lo = (uint32_t)__bfloat16_as_ushort(lx) |
         ((uint32_t)__bfloat16_as_ushort(ly) << 16);
}

__device__ __forceinline__ uint32_t pack_bf16(float x, float y)
{
    return (uint32_t)__bfloat16_as_ushort(__float2bfloat16(x)) |
           ((uint32_t)__bfloat16_as_ushort(__float2bfloat16(y)) << 16);
}

#define MMA_BF16(d, a, b)                                                   \
    asm volatile(                                                           \
        "mma.sync.aligned.m16n8k16.row.col.f32.bf16.bf16.f32 "              \
        "{%0,%1,%2,%3}, {%4,%5,%6,%7}, {%8,%9}, {%0,%1,%2,%3};"             \
        : "+f"(d[0]), "+f"(d[1]), "+f"(d[2]), "+f"(d[3])                    \
        : "r"(a[0]), "r"(a[1]), "r"(a[2]), "r"(a[3]), "r"(b[0]), "r"(b[1]))

#define LDSM_X4(R, addr)                                                    \
    asm volatile("ldmatrix.sync.aligned.m8n8.x4.shared.b16 "                \
                 "{%0,%1,%2,%3}, [%4];"                                     \
                 : "=r"(R[0]), "=r"(R[1]), "=r"(R[2]), "=r"(R[3])           \
                 : "r"(addr))

#define LDSM_X4_T(R, addr)                                                  \
    asm volatile("ldmatrix.sync.aligned.m8n8.x4.trans.shared.b16 "          \
                 "{%0,%1,%2,%3}, [%4];"                                     \
                 : "=r"(R[0]), "=r"(R[1]), "=r"(R[2]), "=r"(R[3])           \
                 : "r"(addr))

__device__ __forceinline__ void cp16(uint32_t dst, const void* src)
{
    asm volatile("cp.async.cg.shared.global [%0], [%1], 16;"
                 :: "r"(dst), "l"(src));
}

// GEMM smem tile: 64B rows, XOR chunk swizzle (conflict-free ldmatrix, no pad)
__device__ __forceinline__ uint32_t sw_off(int row, int ch)
{
    return (uint32_t)(row * 64 + ((ch ^ ((row >> 1) & 3)) << 4));
}

// ---------------------------------------------------------------------------
// Conversion kernels
// ---------------------------------------------------------------------------
__global__ void convert_split_kernel(const float* __restrict__ in,
                                     __nv_bfloat16* __restrict__ hi,
                                     __nv_bfloat16* __restrict__ lo,
                                     int npairs)
{
    int i = blockIdx.x * blockDim.x + threadIdx.x;
    if (i >= npairs) return;
    float2 v = ((const float2*)in)[i];
    uint32_t h, l;
    split_pack2(v.x, v.y, h, l);
    ((uint32_t*)hi)[i] = h;
    ((uint32_t*)lo)[i] = l;
}

// W [Kd][Nd] fp32 -> Wt hi/lo bf16 [Nd][Kd].
// qkv_perm: dest row for src col n is (n%3)*1024 + n/3.
__global__ void convert_wT_kernel(const float* __restrict__ W,
                                  __nv_bfloat16* __restrict__ hi,
                                  __nv_bfloat16* __restrict__ lo,
                                  int Kd, int Nd, int qkv_perm)
{
    __shared__ float t[32][33];
    const int tx = threadIdx.x, ty = threadIdx.y;
    const int n0 = blockIdx.x * 32, k0 = blockIdx.y * 32;
    #pragma unroll
    for (int r = ty; r < 32; r += 8)
        t[r][tx] = W[(size_t)(k0 + r) * Nd + n0 + tx];
    __syncthreads();
    #pragma unroll
    for (int r = ty; r < 32; r += 8) {
        float v = t[tx][r];
        int n = n0 + r;
        int drow = qkv_perm ? ((n % 3) * 1024 + n / 3) : n;
        __nv_bfloat16 h = __float2bfloat16(v);
        hi[(size_t)drow * Kd + k0 + tx] = h;
        lo[(size_t)drow * Kd + k0 + tx] =
            __float2bfloat16(v - __bfloat162float(h));
    }
}

// ---------------------------------------------------------------------------
// Tensor-core GEMM, bf16x3 split, 3-stage cp.async pipeline + ldmatrix,
// swizzled 64B rows -> 98304 B total, 2 CTAs/SM.
// ---------------------------------------------------------------------------
#define ABUF   8192             // 128*64 per array per stage
#define OFF_AH 0
#define OFF_AL 24576            // 3*ABUF
#define OFF_BH 49152
#define OFF_BL 73728
#define GEMM_SMEM_BYTES 98304

__global__ __launch_bounds__(256, 2)
void gemm_mma_kernel(const __nv_bfloat16* __restrict__ Ahi,
                     const __nv_bfloat16* __restrict__ Alo,
                     const __nv_bfloat16* __restrict__ Bhi,
                     const __nv_bfloat16* __restrict__ Blo,
                     const float* __restrict__ bias,
                     float* __restrict__ Cf,
                     __nv_bfloat16* __restrict__ Chi,
                     __nv_bfloat16* __restrict__ Clo,
                     __nv_bfloat16* __restrict__ Qh,
                     __nv_bfloat16* __restrict__ Ql,
                     __nv_bfloat16* __restrict__ Kh,
                     __nv_bfloat16* __restrict__ Kl,
                     __nv_bfloat16* __restrict__ Vb,
                     int N, int K, int relu)
{
    extern __shared__ char smem[];
    const uint32_t sb = (uint32_t)__cvta_generic_to_shared(smem);

    const int tid  = threadIdx.x;
    const int warp = tid >> 5;
    const int lane = tid & 31;
    const int m0   = blockIdx.y * 128;
    const int n0   = blockIdx.x * 128;
    const int wm   = (warp >> 1) * 32;
    const int wn   = (warp & 1) * 64;
    const int tg   = lane & 3;
    const int grp  = lane >> 2;

    float acc[2][8][4];
    #pragma unroll
    for (int i = 0; i < 2; i++)
        #pragma unroll
        for (int j = 0; j < 8; j++)
            #pragma unroll
            for (int q = 0; q < 4; q++) acc[i][j][q] = 0.0f;

    auto issueTile = [&](int k0, int buf) {
        const uint32_t bo = buf * ABUF;
        #pragma unroll
        for (int t = 0; t < 2; t++) {
            int q   = tid + t * 256;        // 0..511
            int row = q >> 2, ch = q & 3;
            uint32_t so = bo + sw_off(row, ch);
            size_t ao  = (size_t)(m0 + row) * K + k0 + ch * 8;
            size_t bo2 = (size_t)(n0 + row) * K + k0 + ch * 8;
            cp16(sb + OFF_AH + so, Ahi + ao);
            cp16(sb + OFF_AL + so, Alo + ao);
            cp16(sb + OFF_BH + so, Bhi + bo2);
            cp16(sb + OFF_BL + so, Blo + bo2);
        }
    };

    auto computeTile = [&](int buf) {
        const uint32_t bo = buf * ABUF;
        const int rr = lane & 15;
        const int cs = lane >> 4;           // chunk sub-index 0/1
        #pragma unroll
        for (int kc = 0; kc < 2; kc++) {
            const int ch = kc * 2 + cs;
            uint32_t ah[2][4], al[2][4];
            #pragma unroll
            for (int i = 0; i < 2; i++) {
                uint32_t ad = sb + bo + sw_off(wm + i * 16 + rr, ch);
                LDSM_X4(ah[i], ad + OFF_AH);
                LDSM_X4(al[i], ad + OFF_AL);
            }
            #pragma unroll
            for (int jj = 0; jj < 4; jj++) {
                uint32_t bd = sb + bo + sw_off(wn + jj * 16 + rr, ch);
                uint32_t bh[4], bl[4];
                LDSM_X4(bh, bd + OFF_BH);
                LDSM_X4(bl, bd + OFF_BL);
                uint32_t bh0[2] = { bh[0], bh[2] }, bh1[2] = { bh[1], bh[3] };
                uint32_t bl0[2] = { bl[0], bl[2] }, bl1[2] = { bl[1], bl[3] };
                #pragma unroll
                for (int i = 0; i < 2; i++) {
                    MMA_BF16(acc[i][2*jj],   ah[i], bh0);
                    MMA_BF16(acc[i][2*jj],   ah[i], bl0);
                    MMA_BF16(acc[i][2*jj],   al[i], bh0);
                    MMA_BF16(acc[i][2*jj+1], ah[i], bh1);
                    MMA_BF16(acc[i][2*jj+1], ah[i], bl1);
                    MMA_BF16(acc[i][2*jj+1], al[i], bh1);
                }
            }
        }
    };

    const int nIter = K >> 5;   // >= 32 for all our GEMMs
    issueTile(0, 0);
    asm volatile("cp.async.commit_group;");
    issueTile(32, 1);
    asm volatile("cp.async.commit_group;");

    for (int it = 0; it < nIter; it++) {
        const int buf = it % 3;
        asm volatile("cp.async.wait_group 1;");
        __syncthreads();
        if (it + 2 < nIter) {
            issueTile((it + 2) << 5, (it + 2) % 3);
            asm volatile("cp.async.commit_group;");
        }
        computeTile(buf);
    }

    // ---- epilogue ----
    #pragma unroll
    for (int i = 0; i < 2; i++) {
        int r = m0 + wm + i * 16 + grp;
        #pragma unroll
        for (int j = 0; j < 8; j++) {
            int c = n0 + wn + j * 8 + tg * 2;
            if (Qh) {
                int comp = c >> 10, cd = c & 1023;
                float b0 = bias[cd * 3 + comp], b1 = bias[(cd + 1) * 3 + comp];
                float v0 = acc[i][j][0] + b0, v1 = acc[i][j][1] + b1;
                float v2 = acc[i][j][2] + b0, v3 = acc[i][j][3] + b1;
                size_t o0 = (size_t)r * DM + cd;
                size_t o1 = (size_t)(r + 8) * DM + cd;
                uint32_t h, l;
                if (comp == 0) {
                    split_pack2(v0 * QSCALE, v1 * QSCALE, h, l);
                    *(uint32_t*)&Qh[o0] = h; *(uint32_t*)&Ql[o0] = l;
                    split_pack2(v2 * QSCALE, v3 * QSCALE, h, l);
                    *(uint32_t*)&Qh[o1] = h; *(uint32_t*)&Ql[o1] = l;
                } else if (comp == 1) {
                    split_pack2(v0, v1, h, l);
                    *(uint32_t*)&Kh[o0] = h; *(uint32_t*)&Kl[o0] = l;
                    split_pack2(v2, v3, h, l);
                    *(uint32_t*)&Kh[o1] = h; *(uint32_t*)&Kl[o1] = l;
                } else {
                    *(uint32_t*)&Vb[o0] = pack_bf16(v0, v1);
                    *(uint32_t*)&Vb[o1] = pack_bf16(v2, v3);
                }
            } else {
                float b0 = bias[c], b1 = bias[c + 1];
                float v0 = acc[i][j][0] + b0, v1 = acc[i][j][1] + b1;
                float v2 = acc[i][j][2] + b0, v3 = acc[i][j][3] + b1;
                if (relu) {
                    v0 = fmaxf(v0, 0.0f); v1 = fmaxf(v1, 0.0f);
                    v2 = fmaxf(v2, 0.0f); v3 = fmaxf(v3, 0.0f);
                }
                if (Cf) {
                    *(float2*)&Cf[(size_t)r * N + c]       = make_float2(v0, v1);
                    *(float2*)&Cf[(size_t)(r + 8) * N + c] = make_float2(v2, v3);
                } else {
                    uint32_t h, l;
                    split_pack2(v0, v1, h, l);
                    *(uint32_t*)&Chi[(size_t)r * N + c] = h;
                    *(uint32_t*)&Clo[(size_t)r * N + c] = l;
                    split_pack2(v2, v3, h, l);
                    *(uint32_t*)&Chi[(size_t)(r + 8) * N + c] = h;
                    *(uint32_t*)&Clo[(size_t)(r + 8) * N + c] = l;
                }
            }
        }
    }
}

// ---------------------------------------------------------------------------
// Tensor-core flash attention, 3-stage KV pipeline, exp2 softmax.
// Grid (T/128, H, N), 256 threads, 2 CTAs/SM. Q pre-scaled by 0.125*log2e.
// ---------------------------------------------------------------------------
#define ATT_SROW 144
#define ATT_KBUF 27648          // per buf: Kh 9216 | Kl 9216 | V 9216
#define ATT_SMEM 82944          // 3 buffers

__global__ __launch_bounds__(256, 2)
void attention_mma_kernel(const __nv_bfloat16* __restrict__ Qh,
                          const __nv_bfloat16* __restrict__ Ql,
                          const __nv_bfloat16* __restrict__ Kh,
                          const __nv_bfloat16* __restrict__ Kl,
                          const __nv_bfloat16* __restrict__ Vb,
                          float* __restrict__ ctx)
{
    extern __shared__ char smem[];
    const uint32_t sb = (uint32_t)__cvta_generic_to_shared(smem);

    const int tid  = threadIdx.x;
    const int warp = tid >> 5;
    const int lane = tid & 31;
    const int tg   = lane & 3;
    const int grp  = lane >> 2;
    const int wm   = warp * 16;
    const int rr   = lane & 15;
    const int kb   = (lane >> 4) << 4;

    const int q0 = blockIdx.x * 128;
    const int h  = blockIdx.y;
    const int n  = blockIdx.z;
    const int h64 = h * HD;
    const size_t row_base = (size_t)n * T_SEQ;

    // ---- stage Q (hi at 0, lo at 18432), extract resident fragments ----
    #pragma unroll
    for (int t = 0; t < 4; t++) {
        int u = tid + t * 256;
        int row = u >> 3, ch = u & 7;
        size_t g = (size_t)(row_base + q0 + row) * DM + h64 + ch * 8;
        uint32_t so = row * ATT_SROW + ch * 16;
        cp16(sb + so, Qh + g);
        cp16(sb + 18432 + so, Ql + g);
    }
    asm volatile("cp.async.commit_group;");
    asm volatile("cp.async.wait_group 0;");
    __syncthreads();

    uint32_t qfh[4][4], qfl[4][4];
    #pragma unroll
    for (int kc = 0; kc < 4; kc++) {
        uint32_t ad = sb + (wm + rr) * ATT_SROW + kc * 32 + kb;
        LDSM_X4(qfh[kc], ad);
        LDSM_X4(qfl[kc], ad + 18432);
    }
    __syncthreads();   // Q consumed before KV buffers overwrite the region

    auto issueKV = [&](int kt, int buf) {
        uint32_t bo = sb + buf * ATT_KBUF;
        int kv0 = kt * 64;
        #pragma unroll
        for (int t = 0; t < 2; t++) {
            int u = tid + t * 256;
            int row = u >> 3, ch = u & 7;
            size_t g = (size_t)(row_base + kv0 + row) * DM + h64 + ch * 8;
            uint32_t so = row * ATT_SROW + ch * 16;
            cp16(bo + so,         Kh + g);
            cp16(bo + 9216 + so,  Kl + g);
            cp16(bo + 18432 + so, Vb + g);
        }
    };

    float o[8][4];
    #pragma unroll
    for (int j = 0; j < 8; j++)
        #pragma unroll
        for (int q = 0; q < 4; q++) o[j][q] = 0.0f;
    float m0 = -1e30f, m1 = -1e30f, l0 = 0.0f, l1 = 0.0f;

    const int nTiles = T_SEQ / 64;
    issueKV(0, 0);
    asm volatile("cp.async.commit_group;");
    issueKV(1, 1);
    asm volatile("cp.async.commit_group;");

    for (int kt = 0; kt < nTiles; kt++) {
        const int buf = kt % 3;
        asm volatile("cp.async.wait_group 1;");
        __syncthreads();
        if (kt + 2 < nTiles) {
            issueKV(kt + 2, (kt + 2) % 3);
            asm volatile("cp.async.commit_group;");
        }

        const uint32_t bo = sb + buf * ATT_KBUF;

        // ---- S = Q @ K^T (log2-domain logits) ----
        float s[8][4];
        #pragma unroll
        for (int j = 0; j < 8; j++)
            #pragma unroll
            for (int q = 0; q < 4; q++) s[j][q] = 0.0f;
        #pragma unroll
        for (int jj = 0; jj < 4; jj++) {
            #pragma unroll
            for (int kc = 0; kc < 4; kc++) {
                uint32_t ad = bo + (jj * 16 + rr) * ATT_SROW + kc * 32 + kb;
                uint32_t bh[4], bl[4];
                LDSM_X4(bh, ad);
                LDSM_X4(bl, ad + 9216);
                uint32_t bh0[2] = { bh[0], bh[2] }, bh1[2] = { bh[1], bh[3] };
                uint32_t bl0[2] = { bl[0], bl[2] }, bl1[2] = { bl[1], bl[3] };
                MMA_BF16(s[2*jj],   qfh[kc], bh0);
                MMA_BF16(s[2*jj],   qfh[kc], bl0);
                MMA_BF16(s[2*jj],   qfl[kc], bh0);
                MMA_BF16(s[2*jj+1], qfh[kc], bh1);
                MMA_BF16(s[2*jj+1], qfh[kc], bl1);
                MMA_BF16(s[2*jj+1], qfl[kc], bh1);
            }
        }

        // ---- online softmax (base-2) ----
        float mx0 = -1e30f, mx1 = -1e30f;
        #pragma unroll
        for (int j = 0; j < 8; j++) {
            mx0 = fmaxf(mx0, fmaxf(s[j][0], s[j][1]));
            mx1 = fmaxf(mx1, fmaxf(s[j][2], s[j][3]));
        }
        mx0 = fmaxf(mx0, __shfl_xor_sync(0xffffffff, mx0, 1));
        mx0 = fmaxf(mx0, __shfl_xor_sync(0xffffffff, mx0, 2));
        mx1 = fmaxf(mx1, __shfl_xor_sync(0xffffffff, mx1, 1));
        mx1 = fmaxf(mx1, __shfl_xor_sync(0xffffffff, mx1, 2));
        float mn0 = fmaxf(m0, mx0), mn1 = fmaxf(m1, mx1);
        float al0 = exp2f(m0 - mn0), al1 = exp2f(m1 - mn1);
        float sum0 = 0.0f, sum1 = 0.0f;
        #pragma unroll
        for (int j = 0; j < 8; j++) {
            s[j][0] = exp2f(s[j][0] - mn0);
            s[j][1] = exp2f(s[j][1] - mn0);
            s[j][2] = exp2f(s[j][2] - mn1);
            s[j][3] = exp2f(s[j][3] - mn1);
            sum0 += s[j][0] + s[j][1];
            sum1 += s[j][2] + s[j][3];
        }
        sum0 += __shfl_xor_sync(0xffffffff, sum0, 1);
        sum0 += __shfl_xor_sync(0xffffffff, sum0, 2);
        sum1 += __shfl_xor_sync(0xffffffff, sum1, 1);
        sum1 += __shfl_xor_sync(0xffffffff, sum1, 2);
        m0 = mn0; m1 = mn1;
        l0 = l0 * al0 + sum0;
        l1 = l1 * al1 + sum1;
        #pragma unroll
        for (int j = 0; j < 8; j++) {
            o[j][0] *= al0; o[j][1] *= al0;
            o[j][2] *= al1; o[j][3] *= al1;
        }

        // ---- P fragments + PV (V via ldmatrix.trans) ----
        uint32_t ap[4][4];
        #pragma unroll
        for (int kc = 0; kc < 4; kc++) {
            ap[kc][0] = pack_bf16(s[2*kc][0],   s[2*kc][1]);
            ap[kc][1] = pack_bf16(s[2*kc][2],   s[2*kc][3]);
            ap[kc][2] = pack_bf16(s[2*kc+1][0], s[2*kc+1][1]);
            ap[kc][3] = pack_bf16(s[2*kc+1][2], s[2*kc+1][3]);
        }
        const uint32_t vrow = ((lane >> 4) << 3) + (lane & 7);
        const uint32_t vcol = ((lane >> 3) & 1) << 3;
        #pragma unroll
        for (int jd = 0; jd < 4; jd++) {
            #pragma unroll
            for (int kc = 0; kc < 4; kc++) {
                uint32_t va = bo + 18432 + (kc * 16 + vrow) * ATT_SROW
                            + (jd * 16 + vcol) * 2;
                uint32_t vr[4];
                LDSM_X4_T(vr, va);
                uint32_t vg0[2] = { vr[0], vr[2] }, vg1[2] = { vr[1], vr[3] };
                MMA_BF16(o[2*jd],   ap[kc], vg0);
                MMA_BF16(o[2*jd+1], ap[kc], vg1);
            }
        }
    }

    // ---- epilogue ----
    float inv0 = 1.0f / l0, inv1 = 1.0f / l1;
    size_t r0 = (row_base + q0 + wm + grp) * (size_t)DM + h64;
    size_t r1 = r0 + 8 * (size_t)DM;
    #pragma unroll
    for (int j = 0; j < 8; j++) {
        int c = j * 8 + tg * 2;
        *(float2*)&ctx[r0 + c] = make_float2(o[j][0] * inv0, o[j][1] * inv0);
        *(float2*)&ctx[r1 + c] = make_float2(o[j][2] * inv1, o[j][3] * inv1);
    }
}

// ---------------------------------------------------------------------------
// out = LayerNorm(a + b) * gamma + beta; optional hi/lo bf16 side outputs.
// ---------------------------------------------------------------------------
__global__ void add_ln_kernel(const float* __restrict__ a,
                              const float* __restrict__ b,
                              const float* __restrict__ gamma,
                              const float* __restrict__ beta,
                              float* __restrict__ out,
                              __nv_bfloat16* __restrict__ ohi,
                              __nv_bfloat16* __restrict__ olo)
{
    __shared__ float red[256];
    const int row = blockIdx.x;
    const int tid = threadIdx.x;
    const size_t base = (size_t)row * DM;

    float v[4];
    float s = 0.0f;
    #pragma unroll
    for (int i = 0; i < 4; i++) {
        int c = tid + 256 * i;
        v[i] = a[base + c] + b[base + c];
        s += v[i];
    }
    red[tid] = s;
    __syncthreads();
    #pragma unroll
    for (int off = 128; off > 0; off >>= 1) {
        if (tid < off) red[tid] += red[tid + off];
        __syncthreads();
    }
    const float mu = red[0] * (1.0f / DM);
    __syncthreads();

    float s2 = 0.0f;
    #pragma unroll
    for (int i = 0; i < 4; i++) {
        float d = v[i] - mu;
        s2 += d * d;
    }
    red[tid] = s2;
    __syncthreads();
    #pragma unroll
    for (int off = 128; off > 0; off >>= 1) {
        if (tid < off) red[tid] += red[tid + off];
        __syncthreads();
    }
    const float rs = rsqrtf(red[0] * (1.0f / DM) + LN_EPS);

    #pragma unroll
    for (int i = 0; i < 4; i++) {
        int c = tid + 256 * i;
        float y = (v[i] - mu) * rs * gamma[c] + beta[c];
        out[base + c] = y;
        if (ohi) {
            __nv_bfloat16 hb = __float2bfloat16(y);
            ohi[base + c] = hb;
            olo[base + c] = __float2bfloat16(y - __bfloat162float(hb));
        }
    }
}

// ---------------------------------------------------------------------------
// Launch
// ---------------------------------------------------------------------------
extern "C" void kernel_launch(void* const* d_in, const int* in_sizes, int n_in,
                              void* d_out, int out_size)
{
    const float* x     = (const float*)d_in[0];
    /* mask = d_in[1] : query-axis mask -> softmax shift -> no-op */
    const float* w_qkv = (const float*)d_in[2];
    const float* b_qkv = (const float*)d_in[3];
    const float* w_ff  = (const float*)d_in[4];
    const float* b_ff  = (const float*)d_in[5];
    const float* w_out = (const float*)d_in[6];
    const float* b_out = (const float*)d_in[7];
    const float* ln1_g = (const float*)d_in[8];
    const float* ln1_b = (const float*)d_in[9];
    const float* ln2_g = (const float*)d_in[10];
    const float* ln2_b = (const float*)d_in[11];
    float* out = (float*)d_out;

    float *ctx, *h1, *tmp;
    __nv_bfloat16 *ahi, *alo, *bhi, *blo, *ffhi, *fflo;
    __nv_bfloat16 *qh, *ql, *kh, *kl, *vb;
    cudaGetSymbolAddress((void**)&ctx,  g_ctx);
    cudaGetSymbolAddress((void**)&h1,   g_h1);
    cudaGetSymbolAddress((void**)&tmp,  g_tmp);
    cudaGetSymbolAddress((void**)&ahi,  g_ahi);
    cudaGetSymbolAddress((void**)&alo,  g_alo);
    cudaGetSymbolAddress((void**)&bhi,  g_bhi);
    cudaGetSymbolAddress((void**)&blo,  g_blo);
    cudaGetSymbolAddress((void**)&ffhi, g_ffhi);
    cudaGetSymbolAddress((void**)&fflo, g_fflo);
    cudaGetSymbolAddress((void**)&qh,   g_qh);
    cudaGetSymbolAddress((void**)&ql,   g_ql);
    cudaGetSymbolAddress((void**)&kh,   g_kh);
    cudaGetSymbolAddress((void**)&kl,   g_kl);
    cudaGetSymbolAddress((void**)&vb,   g_vb);

    static int smem_set = 0;
    if (!smem_set) {
        cudaFuncSetAttribute(gemm_mma_kernel,
                             cudaFuncAttributeMaxDynamicSharedMemorySize,
                             GEMM_SMEM_BYTES);
        cudaFuncSetAttribute(attention_mma_kernel,
                             cudaFuncAttributeMaxDynamicSharedMemorySize,
                             ATT_SMEM);
        smem_set = 1;
    }

    // 0) Convert x -> hi/lo; w_qkv -> transposed+permuted hi/lo
    convert_split_kernel<<<(NT * DM / 2 + 255) / 256, 256>>>(x, ahi, alo, NT * DM / 2);
    convert_wT_kernel<<<dim3(QKV_N / 32, DM / 32), dim3(32, 8)>>>(w_qkv, bhi, blo, DM, QKV_N, 1);

    // 1) QKV projection -> attention-native bf16 Q/K/V (Q pre-scaled)
    gemm_mma_kernel<<<dim3(QKV_N / 128, NT / 128), 256, GEMM_SMEM_BYTES>>>(
        ahi, alo, bhi, blo, b_qkv, nullptr, nullptr, nullptr,
        qh, ql, kh, kl, vb, QKV_N, DM, 0);

    // 2) Attention
    attention_mma_kernel<<<dim3(T_SEQ / 128, H_NUM, NB), 256, ATT_SMEM>>>(
        qh, ql, kh, kl, vb, ctx);

    // 3) h1 = LN(x + ctx), emit h1 hi/lo
    add_ln_kernel<<<NT, 256>>>(x, ctx, ln1_g, ln1_b, h1, ahi, alo);

    // 4) ff = relu(h1 @ w_ff + b_ff) -> hi/lo bf16
    convert_wT_kernel<<<dim3(DFF / 32, DM / 32), dim3(32, 8)>>>(w_ff, bhi, blo, DM, DFF, 0);
    gemm_mma_kernel<<<dim3(DFF / 128, NT / 128), 256, GEMM_SMEM_BYTES>>>(
        ahi, alo, bhi, blo, b_ff, nullptr, ffhi, fflo,
        nullptr, nullptr, nullptr, nullptr, nullptr, DFF, DM, 1);

    // 5) tmp = ff @ w_out + b_out -> fp32
    convert_wT_kernel<<<dim3(DM / 32, DFF / 32), dim3(32, 8)>>>(w_out, bhi, blo, DFF, DM, 0);
    gemm_mma_kernel<<<dim3(DM / 128, NT / 128), 256, GEMM_SMEM_BYTES>>>(
        ffhi, fflo, bhi, blo, b_out, tmp, nullptr, nullptr,
        nullptr, nullptr, nullptr, nullptr, nullptr, DM, DFF, 0);

    // 6) out = LN(h1 + tmp)
    add_ln_kernel<<<NT, 256>>>(h1, tmp, ln2_g, ln2_b, out, nullptr, nullptr);
}

// round 9
// speedup vs baseline: 1.2647x; 1.0765x over previous
#include <cuda_runtime.h>
#include <cuda_bf16.h>
#include <math.h>
#include <stdint.h>

// ---------------------------------------------------------------------------
// Problem constants
// ---------------------------------------------------------------------------
#define NB      2
#define T_SEQ   2048
#define NT      (NB * T_SEQ)        // 4096 tokens
#define DM      1024
#define H_NUM   16
#define HD      64
#define DFF     4096
#define QKV_N   (3 * DM)            // 3072
#define LN_EPS  1e-3f
#define QSCALE  0.18033688011112042f   // 0.125 * log2(e)

// ---------------------------------------------------------------------------
// Scratch
// ---------------------------------------------------------------------------
__device__ float g_ctx[NT * DM];
__device__ float g_h1 [NT * DM];
__device__ float g_tmp[NT * DM];
__device__ __nv_bfloat16 g_ahi[NT * DM];
__device__ __nv_bfloat16 g_alo[NT * DM];
__device__ __nv_bfloat16 g_bhi[4 * 1024 * 1024];
__device__ __nv_bfloat16 g_blo[4 * 1024 * 1024];
__device__ __nv_bfloat16 g_ffhi[NT * DFF];
__device__ __nv_bfloat16 g_fflo[NT * DFF];
// attention-native QKV (plain bf16, layout [token][h*64+d])
__device__ __nv_bfloat16 g_qb[NT * DM];
__device__ __nv_bfloat16 g_kb[NT * DM];
__device__ __nv_bfloat16 g_vb[NT * DM];

// ---------------------------------------------------------------------------
// Helpers
// ---------------------------------------------------------------------------
__device__ __forceinline__ void split_pack2(float x, float y,
                                            uint32_t& hi, uint32_t& lo)
{
    __nv_bfloat16 hx = __float2bfloat16(x);
    __nv_bfloat16 hy = __float2bfloat16(y);
    __nv_bfloat16 lx = __float2bfloat16(x - __bfloat162float(hx));
    __nv_bfloat16 ly = __float2bfloat16(y - __bfloat162float(hy));
    hi = (uint32_t)__bfloat16_as_ushort(hx) |
         ((uint32_t)__bfloat16_as_ushort(hy) << 16);
    lo = (uint32_t)__bfloat16_as_ushort(lx) |
         ((uint32_t)__bfloat16_as_ushort(ly) << 16);
}

__device__ __forceinline__ uint32_t pack_bf16(float x, float y)
{
    return (uint32_t)__bfloat16_as_ushort(__float2bfloat16(x)) |
           ((uint32_t)__bfloat16_as_ushort(__float2bfloat16(y)) << 16);
}

#define MMA_BF16(d, a, b)                                                   \
    asm volatile(                                                           \
        "mma.sync.aligned.m16n8k16.row.col.f32.bf16.bf16.f32 "              \
        "{%0,%1,%2,%3}, {%4,%5,%6,%7}, {%8,%9}, {%0,%1,%2,%3};"             \
        : "+f"(d[0]), "+f"(d[1]), "+f"(d[2]), "+f"(d[3])                    \
        : "r"(a[0]), "r"(a[1]), "r"(a[2]), "r"(a[3]), "r"(b[0]), "r"(b[1]))

#define LDSM_X4(R, addr)                                                    \
    asm volatile("ldmatrix.sync.aligned.m8n8.x4.shared.b16 "                \
                 "{%0,%1,%2,%3}, [%4];"                                     \
                 : "=r"(R[0]), "=r"(R[1]), "=r"(R[2]), "=r"(R[3])           \
                 : "r"(addr))

#define LDSM_X4_T(R, addr)                                                  \
    asm volatile("ldmatrix.sync.aligned.m8n8.x4.trans.shared.b16 "          \
                 "{%0,%1,%2,%3}, [%4];"                                     \
                 : "=r"(R[0]), "=r"(R[1]), "=r"(R[2]), "=r"(R[3])           \
                 : "r"(addr))

__device__ __forceinline__ void cp16(uint32_t dst, const void* src)
{
    asm volatile("cp.async.cg.shared.global [%0], [%1], 16;"
                 :: "r"(dst), "l"(src));
}

// GEMM smem tile: 64B rows, XOR chunk swizzle (conflict-free ldmatrix, no pad)
__device__ __forceinline__ uint32_t sw_off(int row, int ch)
{
    return (uint32_t)(row * 64 + ((ch ^ ((row >> 1) & 3)) << 4));
}

// ---------------------------------------------------------------------------
// Conversion kernels
// ---------------------------------------------------------------------------
__global__ void convert_split_kernel(const float* __restrict__ in,
                                     __nv_bfloat16* __restrict__ hi,
                                     __nv_bfloat16* __restrict__ lo,
                                     int npairs)
{
    int i = blockIdx.x * blockDim.x + threadIdx.x;
    if (i >= npairs) return;
    float2 v = ((const float2*)in)[i];
    uint32_t h, l;
    split_pack2(v.x, v.y, h, l);
    ((uint32_t*)hi)[i] = h;
    ((uint32_t*)lo)[i] = l;
}

// W [Kd][Nd] fp32 -> Wt hi/lo bf16 [Nd][Kd].
// qkv_perm: dest row for src col n is (n%3)*1024 + n/3.
__global__ void convert_wT_kernel(const float* __restrict__ W,
                                  __nv_bfloat16* __restrict__ hi,
                                  __nv_bfloat16* __restrict__ lo,
                                  int Kd, int Nd, int qkv_perm)
{
    __shared__ float t[32][33];
    const int tx = threadIdx.x, ty = threadIdx.y;
    const int n0 = blockIdx.x * 32, k0 = blockIdx.y * 32;
    #pragma unroll
    for (int r = ty; r < 32; r += 8)
        t[r][tx] = W[(size_t)(k0 + r) * Nd + n0 + tx];
    __syncthreads();
    #pragma unroll
    for (int r = ty; r < 32; r += 8) {
        float v = t[tx][r];
        int n = n0 + r;
        int drow = qkv_perm ? ((n % 3) * 1024 + n / 3) : n;
        __nv_bfloat16 h = __float2bfloat16(v);
        hi[(size_t)drow * Kd + k0 + tx] = h;
        lo[(size_t)drow * Kd + k0 + tx] =
            __float2bfloat16(v - __bfloat162float(h));
    }
}

// ---------------------------------------------------------------------------
// Tensor-core GEMM, bf16x3 split, 3-stage cp.async pipeline + ldmatrix,
// swizzled 64B rows -> 98304 B total, 2 CTAs/SM.
// ---------------------------------------------------------------------------
#define ABUF   8192             // 128*64 per array per stage
#define OFF_AH 0
#define OFF_AL 24576            // 3*ABUF
#define OFF_BH 49152
#define OFF_BL 73728
#define GEMM_SMEM_BYTES 98304

__global__ __launch_bounds__(256, 2)
void gemm_mma_kernel(const __nv_bfloat16* __restrict__ Ahi,
                     const __nv_bfloat16* __restrict__ Alo,
                     const __nv_bfloat16* __restrict__ Bhi,
                     const __nv_bfloat16* __restrict__ Blo,
                     const float* __restrict__ bias,
                     float* __restrict__ Cf,
                     __nv_bfloat16* __restrict__ Chi,
                     __nv_bfloat16* __restrict__ Clo,
                     __nv_bfloat16* __restrict__ Qb,
                     __nv_bfloat16* __restrict__ Kb,
                     __nv_bfloat16* __restrict__ Vb,
                     int N, int K, int relu)
{
    extern __shared__ char smem[];
    const uint32_t sb = (uint32_t)__cvta_generic_to_shared(smem);

    const int tid  = threadIdx.x;
    const int warp = tid >> 5;
    const int lane = tid & 31;
    const int m0   = blockIdx.y * 128;
    const int n0   = blockIdx.x * 128;
    const int wm   = (warp >> 1) * 32;
    const int wn   = (warp & 1) * 64;
    const int tg   = lane & 3;
    const int grp  = lane >> 2;

    float acc[2][8][4];
    #pragma unroll
    for (int i = 0; i < 2; i++)
        #pragma unroll
        for (int j = 0; j < 8; j++)
            #pragma unroll
            for (int q = 0; q < 4; q++) acc[i][j][q] = 0.0f;

    auto issueTile = [&](int k0, int buf) {
        const uint32_t bo = buf * ABUF;
        #pragma unroll
        for (int t = 0; t < 2; t++) {
            int q   = tid + t * 256;        // 0..511
            int row = q >> 2, ch = q & 3;
            uint32_t so = bo + sw_off(row, ch);
            size_t ao  = (size_t)(m0 + row) * K + k0 + ch * 8;
            size_t bo2 = (size_t)(n0 + row) * K + k0 + ch * 8;
            cp16(sb + OFF_AH + so, Ahi + ao);
            cp16(sb + OFF_AL + so, Alo + ao);
            cp16(sb + OFF_BH + so, Bhi + bo2);
            cp16(sb + OFF_BL + so, Blo + bo2);
        }
    };

    auto computeTile = [&](int buf) {
        const uint32_t bo = buf * ABUF;
        const int rr = lane & 15;
        const int cs = lane >> 4;           // chunk sub-index 0/1
        #pragma unroll
        for (int kc = 0; kc < 2; kc++) {
            const int ch = kc * 2 + cs;
            uint32_t ah[2][4], al[2][4];
            #pragma unroll
            for (int i = 0; i < 2; i++) {
                uint32_t ad = sb + bo + sw_off(wm + i * 16 + rr, ch);
                LDSM_X4(ah[i], ad + OFF_AH);
                LDSM_X4(al[i], ad + OFF_AL);
            }
            #pragma unroll
            for (int jj = 0; jj < 4; jj++) {
                uint32_t bd = sb + bo + sw_off(wn + jj * 16 + rr, ch);
                uint32_t bh[4], bl[4];
                LDSM_X4(bh, bd + OFF_BH);
                LDSM_X4(bl, bd + OFF_BL);
                uint32_t bh0[2] = { bh[0], bh[2] }, bh1[2] = { bh[1], bh[3] };
                uint32_t bl0[2] = { bl[0], bl[2] }, bl1[2] = { bl[1], bl[3] };
                #pragma unroll
                for (int i = 0; i < 2; i++) {
                    MMA_BF16(acc[i][2*jj],   ah[i], bh0);
                    MMA_BF16(acc[i][2*jj],   ah[i], bl0);
                    MMA_BF16(acc[i][2*jj],   al[i], bh0);
                    MMA_BF16(acc[i][2*jj+1], ah[i], bh1);
                    MMA_BF16(acc[i][2*jj+1], ah[i], bl1);
                    MMA_BF16(acc[i][2*jj+1], al[i], bh1);
                }
            }
        }
    };

    const int nIter = K >> 5;   // >= 32 for all our GEMMs
    issueTile(0, 0);
    asm volatile("cp.async.commit_group;");
    issueTile(32, 1);
    asm volatile("cp.async.commit_group;");

    for (int it = 0; it < nIter; it++) {
        const int buf = it % 3;
        asm volatile("cp.async.wait_group 1;");
        __syncthreads();
        if (it + 2 < nIter) {
            issueTile((it + 2) << 5, (it + 2) % 3);
            asm volatile("cp.async.commit_group;");
        }
        computeTile(buf);
    }

    // ---- epilogue ----
    #pragma unroll
    for (int i = 0; i < 2; i++) {
        int r = m0 + wm + i * 16 + grp;
        #pragma unroll
        for (int j = 0; j < 8; j++) {
            int c = n0 + wn + j * 8 + tg * 2;
            if (Qb) {
                // qkv mode: c is comp-major permuted column; plain bf16 out
                int comp = c >> 10, cd = c & 1023;
                float b0 = bias[cd * 3 + comp], b1 = bias[(cd + 1) * 3 + comp];
                float v0 = acc[i][j][0] + b0, v1 = acc[i][j][1] + b1;
                float v2 = acc[i][j][2] + b0, v3 = acc[i][j][3] + b1;
                size_t o0 = (size_t)r * DM + cd;
                size_t o1 = (size_t)(r + 8) * DM + cd;
                __nv_bfloat16* dst = (comp == 0) ? Qb : (comp == 1) ? Kb : Vb;
                float sc = (comp == 0) ? QSCALE : 1.0f;
                *(uint32_t*)&dst[o0] = pack_bf16(v0 * sc, v1 * sc);
                *(uint32_t*)&dst[o1] = pack_bf16(v2 * sc, v3 * sc);
            } else {
                float b0 = bias[c], b1 = bias[c + 1];
                float v0 = acc[i][j][0] + b0, v1 = acc[i][j][1] + b1;
                float v2 = acc[i][j][2] + b0, v3 = acc[i][j][3] + b1;
                if (relu) {
                    v0 = fmaxf(v0, 0.0f); v1 = fmaxf(v1, 0.0f);
                    v2 = fmaxf(v2, 0.0f); v3 = fmaxf(v3, 0.0f);
                }
                if (Cf) {
                    *(float2*)&Cf[(size_t)r * N + c]       = make_float2(v0, v1);
                    *(float2*)&Cf[(size_t)(r + 8) * N + c] = make_float2(v2, v3);
                } else {
                    uint32_t h, l;
                    split_pack2(v0, v1, h, l);
                    *(uint32_t*)&Chi[(size_t)r * N + c] = h;
                    *(uint32_t*)&Clo[(size_t)r * N + c] = l;
                    split_pack2(v2, v3, h, l);
                    *(uint32_t*)&Chi[(size_t)(r + 8) * N + c] = h;
                    *(uint32_t*)&Clo[(size_t)(r + 8) * N + c] = l;
                }
            }
        }
    }
}

// ---------------------------------------------------------------------------
// Tensor-core flash attention, plain bf16 QK^T + PV, 3-stage KV pipeline,
// exp2 softmax. Grid (T/128, H, N), 256 threads, 2 CTAs/SM.
// ---------------------------------------------------------------------------
#define ATT_SROW 144
#define ATT_KBUF 18432          // per buf: K 9216 | V 9216
#define ATT_SMEM 55296          // 3 buffers

__global__ __launch_bounds__(256, 2)
void attention_mma_kernel(const __nv_bfloat16* __restrict__ Qb,
                          const __nv_bfloat16* __restrict__ Kb,
                          const __nv_bfloat16* __restrict__ Vb,
                          float* __restrict__ ctx)
{
    extern __shared__ char smem[];
    const uint32_t sb = (uint32_t)__cvta_generic_to_shared(smem);

    const int tid  = threadIdx.x;
    const int warp = tid >> 5;
    const int lane = tid & 31;
    const int tg   = lane & 3;
    const int grp  = lane >> 2;
    const int wm   = warp * 16;
    const int rr   = lane & 15;
    const int kb   = (lane >> 4) << 4;

    const int q0 = blockIdx.x * 128;
    const int h  = blockIdx.y;
    const int n  = blockIdx.z;
    const int h64 = h * HD;
    const size_t row_base = (size_t)n * T_SEQ;

    // ---- stage Q (128x64 bf16, 18432 B), extract resident fragments ----
    #pragma unroll
    for (int t = 0; t < 4; t++) {
        int u = tid + t * 256;          // 0..1023
        int row = u >> 3, ch = u & 7;
        size_t g = (size_t)(row_base + q0 + row) * DM + h64 + ch * 8;
        cp16(sb + row * ATT_SROW + ch * 16, Qb + g);
    }
    asm volatile("cp.async.commit_group;");
    asm volatile("cp.async.wait_group 0;");
    __syncthreads();

    uint32_t qf[4][4];
    #pragma unroll
    for (int kc = 0; kc < 4; kc++) {
        uint32_t ad = sb + (wm + rr) * ATT_SROW + kc * 32 + kb;
        LDSM_X4(qf[kc], ad);
    }
    __syncthreads();   // Q consumed before KV buffers overwrite the region

    auto issueKV = [&](int kt, int buf) {
        uint32_t bo = sb + buf * ATT_KBUF;
        int kv0 = kt * 64;
        #pragma unroll
        for (int t = 0; t < 2; t++) {
            int u = tid + t * 256;      // 0..511
            int row = u >> 3, ch = u & 7;
            size_t g = (size_t)(row_base + kv0 + row) * DM + h64 + ch * 8;
            uint32_t so = row * ATT_SROW + ch * 16;
            cp16(bo + so,        Kb + g);
            cp16(bo + 9216 + so, Vb + g);
        }
    };

    float o[8][4];
    #pragma unroll
    for (int j = 0; j < 8; j++)
        #pragma unroll
        for (int q = 0; q < 4; q++) o[j][q] = 0.0f;
    float m0 = -1e30f, m1 = -1e30f, l0 = 0.0f, l1 = 0.0f;

    const int nTiles = T_SEQ / 64;
    issueKV(0, 0);
    asm volatile("cp.async.commit_group;");
    issueKV(1, 1);
    asm volatile("cp.async.commit_group;");

    for (int kt = 0; kt < nTiles; kt++) {
        const int buf = kt % 3;
        asm volatile("cp.async.wait_group 1;");
        __syncthreads();
        if (kt + 2 < nTiles) {
            issueKV(kt + 2, (kt + 2) % 3);
            asm volatile("cp.async.commit_group;");
        }

        const uint32_t bo = sb + buf * ATT_KBUF;

        // ---- S = Q @ K^T (log2-domain logits), plain bf16 ----
        float s[8][4];
        #pragma unroll
        for (int j = 0; j < 8; j++)
            #pragma unroll
            for (int q = 0; q < 4; q++) s[j][q] = 0.0f;
        #pragma unroll
        for (int jj = 0; jj < 4; jj++) {
            #pragma unroll
            for (int kc = 0; kc < 4; kc++) {
                uint32_t ad = bo + (jj * 16 + rr) * ATT_SROW + kc * 32 + kb;
                uint32_t bh[4];
                LDSM_X4(bh, ad);
                uint32_t bh0[2] = { bh[0], bh[2] }, bh1[2] = { bh[1], bh[3] };
                MMA_BF16(s[2*jj],   qf[kc], bh0);
                MMA_BF16(s[2*jj+1], qf[kc], bh1);
            }
        }

        // ---- online softmax (base-2) ----
        float mx0 = -1e30f, mx1 = -1e30f;
        #pragma unroll
        for (int j = 0; j < 8; j++) {
            mx0 = fmaxf(mx0, fmaxf(s[j][0], s[j][1]));
            mx1 = fmaxf(mx1, fmaxf(s[j][2], s[j][3]));
        }
        mx0 = fmaxf(mx0, __shfl_xor_sync(0xffffffff, mx0, 1));
        mx0 = fmaxf(mx0, __shfl_xor_sync(0xffffffff, mx0, 2));
        mx1 = fmaxf(mx1, __shfl_xor_sync(0xffffffff, mx1, 1));
        mx1 = fmaxf(mx1, __shfl_xor_sync(0xffffffff, mx1, 2));
        float mn0 = fmaxf(m0, mx0), mn1 = fmaxf(m1, mx1);
        float al0 = exp2f(m0 - mn0), al1 = exp2f(m1 - mn1);
        float sum0 = 0.0f, sum1 = 0.0f;
        #pragma unroll
        for (int j = 0; j < 8; j++) {
            s[j][0] = exp2f(s[j][0] - mn0);
            s[j][1] = exp2f(s[j][1] - mn0);
            s[j][2] = exp2f(s[j][2] - mn1);
            s[j][3] = exp2f(s[j][3] - mn1);
            sum0 += s[j][0] + s[j][1];
            sum1 += s[j][2] + s[j][3];
        }
        sum0 += __shfl_xor_sync(0xffffffff, sum0, 1);
        sum0 += __shfl_xor_sync(0xffffffff, sum0, 2);
        sum1 += __shfl_xor_sync(0xffffffff, sum1, 1);
        sum1 += __shfl_xor_sync(0xffffffff, sum1, 2);
        m0 = mn0; m1 = mn1;
        l0 = l0 * al0 + sum0;
        l1 = l1 * al1 + sum1;
        #pragma unroll
        for (int j = 0; j < 8; j++) {
            o[j][0] *= al0; o[j][1] *= al0;
            o[j][2] *= al1; o[j][3] *= al1;
        }

        // ---- P fragments + PV (V via ldmatrix.trans) ----
        uint32_t ap[4][4];
        #pragma unroll
        for (int kc = 0; kc < 4; kc++) {
            ap[kc][0] = pack_bf16(s[2*kc][0],   s[2*kc][1]);
            ap[kc][1] = pack_bf16(s[2*kc][2],   s[2*kc][3]);
            ap[kc][2] = pack_bf16(s[2*kc+1][0], s[2*kc+1][1]);
            ap[kc][3] = pack_bf16(s[2*kc+1][2], s[2*kc+1][3]);
        }
        const uint32_t vrow = ((lane >> 4) << 3) + (lane & 7);
        const uint32_t vcol = ((lane >> 3) & 1) << 3;
        #pragma unroll
        for (int jd = 0; jd < 4; jd++) {
            #pragma unroll
            for (int kc = 0; kc < 4; kc++) {
                uint32_t va = bo + 9216 + (kc * 16 + vrow) * ATT_SROW
                            + (jd * 16 + vcol) * 2;
                uint32_t vr[4];
                LDSM_X4_T(vr, va);
                uint32_t vg0[2] = { vr[0], vr[2] }, vg1[2] = { vr[1], vr[3] };
                MMA_BF16(o[2*jd],   ap[kc], vg0);
                MMA_BF16(o[2*jd+1], ap[kc], vg1);
            }
        }
    }

    // ---- epilogue ----
    float inv0 = 1.0f / l0, inv1 = 1.0f / l1;
    size_t r0 = (row_base + q0 + wm + grp) * (size_t)DM + h64;
    size_t r1 = r0 + 8 * (size_t)DM;
    #pragma unroll
    for (int j = 0; j < 8; j++) {
        int c = j * 8 + tg * 2;
        *(float2*)&ctx[r0 + c] = make_float2(o[j][0] * inv0, o[j][1] * inv0);
        *(float2*)&ctx[r1 + c] = make_float2(o[j][2] * inv1, o[j][3] * inv1);
    }
}

// ---------------------------------------------------------------------------
// out = LayerNorm(a + b) * gamma + beta; optional hi/lo bf16 side outputs.
// ---------------------------------------------------------------------------
__global__ void add_ln_kernel(const float* __restrict__ a,
                              const float* __restrict__ b,
                              const float* __restrict__ gamma,
                              const float* __restrict__ beta,
                              float* __restrict__ out,
                              __nv_bfloat16* __restrict__ ohi,
                              __nv_bfloat16* __restrict__ olo)
{
    __shared__ float red[256];
    const int row = blockIdx.x;
    const int tid = threadIdx.x;
    const size_t base = (size_t)row * DM;

    float v[4];
    float s = 0.0f;
    #pragma unroll
    for (int i = 0; i < 4; i++) {
        int c = tid + 256 * i;
        v[i] = a[base + c] + b[base + c];
        s += v[i];
    }
    red[tid] = s;
    __syncthreads();
    #pragma unroll
    for (int off = 128; off > 0; off >>= 1) {
        if (tid < off) red[tid] += red[tid + off];
        __syncthreads();
    }
    const float mu = red[0] * (1.0f / DM);
    __syncthreads();

    float s2 = 0.0f;
    #pragma unroll
    for (int i = 0; i < 4; i++) {
        float d = v[i] - mu;
        s2 += d * d;
    }
    red[tid] = s2;
    __syncthreads();
    #pragma unroll
    for (int off = 128; off > 0; off >>= 1) {
        if (tid < off) red[tid] += red[tid + off];
        __syncthreads();
    }
    const float rs = rsqrtf(red[0] * (1.0f / DM) + LN_EPS);

    #pragma unroll
    for (int i = 0; i < 4; i++) {
        int c = tid + 256 * i;
        float y = (v[i] - mu) * rs * gamma[c] + beta[c];
        out[base + c] = y;
        if (ohi) {
            __nv_bfloat16 hb = __float2bfloat16(y);
            ohi[base + c] = hb;
            olo[base + c] = __float2bfloat16(y - __bfloat162float(hb));
        }
    }
}

// ---------------------------------------------------------------------------
// Launch
// ---------------------------------------------------------------------------
extern "C" void kernel_launch(void* const* d_in, const int* in_sizes, int n_in,
                              void* d_out, int out_size)
{
    const float* x     = (const float*)d_in[0];
    /* mask = d_in[1] : query-axis mask -> softmax shift -> no-op */
    const float* w_qkv = (const float*)d_in[2];
    const float* b_qkv = (const float*)d_in[3];
    const float* w_ff  = (const float*)d_in[4];
    const float* b_ff  = (const float*)d_in[5];
    const float* w_out = (const float*)d_in[6];
    const float* b_out = (const float*)d_in[7];
    const float* ln1_g = (const float*)d_in[8];
    const float* ln1_b = (const float*)d_in[9];
    const float* ln2_g = (const float*)d_in[10];
    const float* ln2_b = (const float*)d_in[11];
    float* out = (float*)d_out;

    float *ctx, *h1, *tmp;
    __nv_bfloat16 *ahi, *alo, *bhi, *blo, *ffhi, *fflo;
    __nv_bfloat16 *qb, *kb, *vb;
    cudaGetSymbolAddress((void**)&ctx,  g_ctx);
    cudaGetSymbolAddress((void**)&h1,   g_h1);
    cudaGetSymbolAddress((void**)&tmp,  g_tmp);
    cudaGetSymbolAddress((void**)&ahi,  g_ahi);
    cudaGetSymbolAddress((void**)&alo,  g_alo);
    cudaGetSymbolAddress((void**)&bhi,  g_bhi);
    cudaGetSymbolAddress((void**)&blo,  g_blo);
    cudaGetSymbolAddress((void**)&ffhi, g_ffhi);
    cudaGetSymbolAddress((void**)&fflo, g_fflo);
    cudaGetSymbolAddress((void**)&qb,   g_qb);
    cudaGetSymbolAddress((void**)&kb,   g_kb);
    cudaGetSymbolAddress((void**)&vb,   g_vb);

    static int smem_set = 0;
    if (!smem_set) {
        cudaFuncSetAttribute(gemm_mma_kernel,
                             cudaFuncAttributeMaxDynamicSharedMemorySize,
                             GEMM_SMEM_BYTES);
        cudaFuncSetAttribute(attention_mma_kernel,
                             cudaFuncAttributeMaxDynamicSharedMemorySize,
                             ATT_SMEM);
        smem_set = 1;
    }

    // 0) Convert x -> hi/lo; w_qkv -> transposed+permuted hi/lo
    convert_split_kernel<<<(NT * DM / 2 + 255) / 256, 256>>>(x, ahi, alo, NT * DM / 2);
    convert_wT_kernel<<<dim3(QKV_N / 32, DM / 32), dim3(32, 8)>>>(w_qkv, bhi, blo, DM, QKV_N, 1);

    // 1) QKV projection -> attention-native bf16 Q/K/V (Q pre-scaled)
    gemm_mma_kernel<<<dim3(QKV_N / 128, NT / 128), 256, GEMM_SMEM_BYTES>>>(
        ahi, alo, bhi, blo, b_qkv, nullptr, nullptr, nullptr,
        qb, kb, vb, QKV_N, DM, 0);

    // 2) Attention
    attention_mma_kernel<<<dim3(T_SEQ / 128, H_NUM, NB), 256, ATT_SMEM>>>(
        qb, kb, vb, ctx);

    // 3) h1 = LN(x + ctx), emit h1 hi/lo
    add_ln_kernel<<<NT, 256>>>(x, ctx, ln1_g, ln1_b, h1, ahi, alo);

    // 4) ff = relu(h1 @ w_ff + b_ff) -> hi/lo bf16
    convert_wT_kernel<<<dim3(DFF / 32, DM / 32), dim3(32, 8)>>>(w_ff, bhi, blo, DM, DFF, 0);
    gemm_mma_kernel<<<dim3(DFF / 128, NT / 128), 256, GEMM_SMEM_BYTES>>>(
        ahi, alo, bhi, blo, b_ff, nullptr, ffhi, fflo,
        nullptr, nullptr, nullptr, DFF, DM, 1);

    // 5) tmp = ff @ w_out + b_out -> fp32
    convert_wT_kernel<<<dim3(DM / 32, DFF / 32), dim3(32, 8)>>>(w_out, bhi, blo, DFF, DM, 0);
    gemm_mma_kernel<<<dim3(DM / 128, NT / 128), 256, GEMM_SMEM_BYTES>>>(
        ffhi, fflo, bhi, blo, b_out, tmp, nullptr, nullptr,
        nullptr, nullptr, nullptr, DM, DFF, 0);

    // 6) out = LN(h1 + tmp)
    add_ln_kernel<<<NT, 256>>>(h1, tmp, ln2_g, ln2_b, out, nullptr, nullptr);
}

// round 11
// speedup vs baseline: 1.4644x; 1.1578x over previous
#include <cuda_runtime.h>
#include <cuda_bf16.h>
#include <math.h>
#include <stdint.h>

// ---------------------------------------------------------------------------
// Problem constants
// ---------------------------------------------------------------------------
#define NB      2
#define T_SEQ   2048
#define NT      (NB * T_SEQ)        // 4096 tokens
#define DM      1024
#define H_NUM   16
#define HD      64
#define DFF     4096
#define QKV_N   (3 * DM)            // 3072
#define LN_EPS  1e-3f
#define QSCALE  0.18033688011112042f   // 0.125 * log2(e)

// ---------------------------------------------------------------------------
// Scratch
// ---------------------------------------------------------------------------
__device__ float g_ctx[NT * DM];
__device__ float g_h1 [NT * DM];
__device__ float g_tmp[NT * DM];
__device__ __nv_bfloat16 g_ahi[NT * DM];
__device__ __nv_bfloat16 g_alo[NT * DM];
__device__ __nv_bfloat16 g_bhi[4 * 1024 * 1024];
__device__ __nv_bfloat16 g_blo[4 * 1024 * 1024];
__device__ __nv_bfloat16 g_ffhi[NT * DFF];
__device__ __nv_bfloat16 g_fflo[NT * DFF];
// attention-native QKV (plain bf16, layout [token][h*64+d])
__device__ __nv_bfloat16 g_qb[NT * DM];
__device__ __nv_bfloat16 g_kb[NT * DM];
__device__ __nv_bfloat16 g_vb[NT * DM];

// ---------------------------------------------------------------------------
// Helpers
// ---------------------------------------------------------------------------
__device__ __forceinline__ void split_pack2(float x, float y,
                                            uint32_t& hi, uint32_t& lo)
{
    __nv_bfloat16 hx = __float2bfloat16(x);
    __nv_bfloat16 hy = __float2bfloat16(y);
    __nv_bfloat16 lx = __float2bfloat16(x - __bfloat162float(hx));
    __nv_bfloat16 ly = __float2bfloat16(y - __bfloat162float(hy));
    hi = (uint32_t)__bfloat16_as_ushort(hx) |
         ((uint32_t)__bfloat16_as_ushort(hy) << 16);
    lo = (uint32_t)__bfloat16_as_ushort(lx) |
         ((uint32_t)__bfloat16_as_ushort(ly) << 16);
}

__device__ __forceinline__ uint32_t pack_bf16(float x, float y)
{
    return (uint32_t)__bfloat16_as_ushort(__float2bfloat16(x)) |
           ((uint32_t)__bfloat16_as_ushort(__float2bfloat16(y)) << 16);
}

#define MMA_BF16(d, a, b)                                                   \
    asm volatile(                                                           \
        "mma.sync.aligned.m16n8k16.row.col.f32.bf16.bf16.f32 "              \
        "{%0,%1,%2,%3}, {%4,%5,%6,%7}, {%8,%9}, {%0,%1,%2,%3};"             \
        : "+f"(d[0]), "+f"(d[1]), "+f"(d[2]), "+f"(d[3])                    \
        : "r"(a[0]), "r"(a[1]), "r"(a[2]), "r"(a[3]), "r"(b[0]), "r"(b[1]))

#define LDSM_X4(R, addr)                                                    \
    asm volatile("ldmatrix.sync.aligned.m8n8.x4.shared.b16 "                \
                 "{%0,%1,%2,%3}, [%4];"                                     \
                 : "=r"(R[0]), "=r"(R[1]), "=r"(R[2]), "=r"(R[3])           \
                 : "r"(addr))

#define LDSM_X4_T(R, addr)                                                  \
    asm volatile("ldmatrix.sync.aligned.m8n8.x4.trans.shared.b16 "          \
                 "{%0,%1,%2,%3}, [%4];"                                     \
                 : "=r"(R[0]), "=r"(R[1]), "=r"(R[2]), "=r"(R[3])           \
                 : "r"(addr))

__device__ __forceinline__ void cp16(uint32_t dst, const void* src)
{
    asm volatile("cp.async.cg.shared.global [%0], [%1], 16;"
                 :: "r"(dst), "l"(src));
}

// GEMM smem tile: 64B rows, XOR chunk swizzle (conflict-free ldmatrix, no pad)
__device__ __forceinline__ uint32_t sw_off(int row, int ch)
{
    return (uint32_t)(row * 64 + ((ch ^ ((row >> 1) & 3)) << 4));
}

// ---------------------------------------------------------------------------
// Conversion kernels
// ---------------------------------------------------------------------------
__global__ void convert_split_kernel(const float* __restrict__ in,
                                     __nv_bfloat16* __restrict__ hi,
                                     __nv_bfloat16* __restrict__ lo,
                                     int npairs)
{
    int i = blockIdx.x * blockDim.x + threadIdx.x;
    if (i >= npairs) return;
    float2 v = ((const float2*)in)[i];
    uint32_t h, l;
    split_pack2(v.x, v.y, h, l);
    ((uint32_t*)hi)[i] = h;
    ((uint32_t*)lo)[i] = l;
}

// W [Kd][Nd] fp32 -> Wt hi/lo bf16 [Nd][Kd].
// qkv_perm: dest row for src col n is (n%3)*1024 + n/3. write_lo=0 skips lo.
__global__ void convert_wT_kernel(const float* __restrict__ W,
                                  __nv_bfloat16* __restrict__ hi,
                                  __nv_bfloat16* __restrict__ lo,
                                  int Kd, int Nd, int qkv_perm, int write_lo)
{
    __shared__ float t[32][33];
    const int tx = threadIdx.x, ty = threadIdx.y;
    const int n0 = blockIdx.x * 32, k0 = blockIdx.y * 32;
    #pragma unroll
    for (int r = ty; r < 32; r += 8)
        t[r][tx] = W[(size_t)(k0 + r) * Nd + n0 + tx];
    __syncthreads();
    #pragma unroll
    for (int r = ty; r < 32; r += 8) {
        float v = t[tx][r];
        int n = n0 + r;
        int drow = qkv_perm ? ((n % 3) * 1024 + n / 3) : n;
        __nv_bfloat16 h = __float2bfloat16(v);
        hi[(size_t)drow * Kd + k0 + tx] = h;
        if (write_lo)
            lo[(size_t)drow * Kd + k0 + tx] =
                __float2bfloat16(v - __bfloat162float(h));
    }
}

// ---------------------------------------------------------------------------
// Tensor-core GEMM, 3-stage cp.async pipeline + ldmatrix, swizzled 64B rows,
// 2 CTAs/SM. SPLIT=1: bf16x3 precision split (3 MMAs). SPLIT=0: plain bf16.
// ---------------------------------------------------------------------------
#define ABUF   8192             // 128*64 per array per stage
#define OFF_AH 0
#define OFF_AL 24576            // 3*ABUF
#define OFF_BH 49152
#define OFF_BL 73728
#define GEMM_SMEM_BYTES 98304
#define GEMM_SMEM_PLAIN 49152   // only AH + BH regions

template<int SPLIT>
__global__ __launch_bounds__(256, 2)
void gemm_mma_kernel(const __nv_bfloat16* __restrict__ Ahi,
                     const __nv_bfloat16* __restrict__ Alo,
                     const __nv_bfloat16* __restrict__ Bhi,
                     const __nv_bfloat16* __restrict__ Blo,
                     const float* __restrict__ bias,
                     float* __restrict__ Cf,
                     __nv_bfloat16* __restrict__ Chi,
                     __nv_bfloat16* __restrict__ Clo,
                     __nv_bfloat16* __restrict__ Qb,
                     __nv_bfloat16* __restrict__ Kb,
                     __nv_bfloat16* __restrict__ Vb,
                     int N, int K, int relu)
{
    extern __shared__ char smem[];
    const uint32_t sb = (uint32_t)__cvta_generic_to_shared(smem);
    // plain mode packs BH right after AH (3*ABUF each region)
    const uint32_t offBH = SPLIT ? OFF_BH : (uint32_t)(3 * ABUF);

    const int tid  = threadIdx.x;
    const int warp = tid >> 5;
    const int lane = tid & 31;
    const int m0   = blockIdx.y * 128;
    const int n0   = blockIdx.x * 128;
    const int wm   = (warp >> 1) * 32;
    const int wn   = (warp & 1) * 64;
    const int tg   = lane & 3;
    const int grp  = lane >> 2;

    float acc[2][8][4];
    #pragma unroll
    for (int i = 0; i < 2; i++)
        #pragma unroll
        for (int j = 0; j < 8; j++)
            #pragma unroll
            for (int q = 0; q < 4; q++) acc[i][j][q] = 0.0f;

    auto issueTile = [&](int k0, int buf) {
        const uint32_t bo = buf * ABUF;
        #pragma unroll
        for (int t = 0; t < 2; t++) {
            int q   = tid + t * 256;        // 0..511
            int row = q >> 2, ch = q & 3;
            uint32_t so = bo + sw_off(row, ch);
            size_t ao  = (size_t)(m0 + row) * K + k0 + ch * 8;
            size_t bo2 = (size_t)(n0 + row) * K + k0 + ch * 8;
            cp16(sb + OFF_AH + so, Ahi + ao);
            cp16(sb + offBH + so, Bhi + bo2);
            if (SPLIT) {
                cp16(sb + OFF_AL + so, Alo + ao);
                cp16(sb + OFF_BL + so, Blo + bo2);
            }
        }
    };

    auto computeTile = [&](int buf) {
        const uint32_t bo = buf * ABUF;
        const int rr = lane & 15;
        const int cs = lane >> 4;           // chunk sub-index 0/1
        #pragma unroll
        for (int kc = 0; kc < 2; kc++) {
            const int ch = kc * 2 + cs;
            uint32_t ah[2][4], al[2][4];
            #pragma unroll
            for (int i = 0; i < 2; i++) {
                uint32_t ad = sb + bo + sw_off(wm + i * 16 + rr, ch);
                LDSM_X4(ah[i], ad + OFF_AH);
                if (SPLIT) LDSM_X4(al[i], ad + OFF_AL);
            }
            #pragma unroll
            for (int jj = 0; jj < 4; jj++) {
                uint32_t bd = sb + bo + sw_off(wn + jj * 16 + rr, ch);
                uint32_t bh[4];
                LDSM_X4(bh, bd + offBH);
                uint32_t bh0[2] = { bh[0], bh[2] }, bh1[2] = { bh[1], bh[3] };
                if (SPLIT) {
                    uint32_t bl[4];
                    LDSM_X4(bl, bd + OFF_BL);
                    uint32_t bl0[2] = { bl[0], bl[2] }, bl1[2] = { bl[1], bl[3] };
                    #pragma unroll
                    for (int i = 0; i < 2; i++) {
                        MMA_BF16(acc[i][2*jj],   ah[i], bh0);
                        MMA_BF16(acc[i][2*jj],   ah[i], bl0);
                        MMA_BF16(acc[i][2*jj],   al[i], bh0);
                        MMA_BF16(acc[i][2*jj+1], ah[i], bh1);
                        MMA_BF16(acc[i][2*jj+1], ah[i], bl1);
                        MMA_BF16(acc[i][2*jj+1], al[i], bh1);
                    }
                } else {
                    #pragma unroll
                    for (int i = 0; i < 2; i++) {
                        MMA_BF16(acc[i][2*jj],   ah[i], bh0);
                        MMA_BF16(acc[i][2*jj+1], ah[i], bh1);
                    }
                }
            }
        }
    };

    const int nIter = K >> 5;   // >= 32 for all our GEMMs
    issueTile(0, 0);
    asm volatile("cp.async.commit_group;");
    issueTile(32, 1);
    asm volatile("cp.async.commit_group;");

    for (int it = 0; it < nIter; it++) {
        const int buf = it % 3;
        asm volatile("cp.async.wait_group 1;");
        __syncthreads();
        if (it + 2 < nIter) {
            issueTile((it + 2) << 5, (it + 2) % 3);
            asm volatile("cp.async.commit_group;");
        }
        computeTile(buf);
    }

    // ---- epilogue ----
    #pragma unroll
    for (int i = 0; i < 2; i++) {
        int r = m0 + wm + i * 16 + grp;
        #pragma unroll
        for (int j = 0; j < 8; j++) {
            int c = n0 + wn + j * 8 + tg * 2;
            if (Qb) {
                // qkv mode: c is comp-major permuted column; plain bf16 out
                int comp = c >> 10, cd = c & 1023;
                float b0 = bias[cd * 3 + comp], b1 = bias[(cd + 1) * 3 + comp];
                float v0 = acc[i][j][0] + b0, v1 = acc[i][j][1] + b1;
                float v2 = acc[i][j][2] + b0, v3 = acc[i][j][3] + b1;
                size_t o0 = (size_t)r * DM + cd;
                size_t o1 = (size_t)(r + 8) * DM + cd;
                __nv_bfloat16* dst = (comp == 0) ? Qb : (comp == 1) ? Kb : Vb;
                float sc = (comp == 0) ? QSCALE : 1.0f;
                *(uint32_t*)&dst[o0] = pack_bf16(v0 * sc, v1 * sc);
                *(uint32_t*)&dst[o1] = pack_bf16(v2 * sc, v3 * sc);
            } else {
                float b0 = bias[c], b1 = bias[c + 1];
                float v0 = acc[i][j][0] + b0, v1 = acc[i][j][1] + b1;
                float v2 = acc[i][j][2] + b0, v3 = acc[i][j][3] + b1;
                if (relu) {
                    v0 = fmaxf(v0, 0.0f); v1 = fmaxf(v1, 0.0f);
                    v2 = fmaxf(v2, 0.0f); v3 = fmaxf(v3, 0.0f);
                }
                if (Cf) {
                    *(float2*)&Cf[(size_t)r * N + c]       = make_float2(v0, v1);
                    *(float2*)&Cf[(size_t)(r + 8) * N + c] = make_float2(v2, v3);
                } else {
                    uint32_t h, l;
                    split_pack2(v0, v1, h, l);
                    *(uint32_t*)&Chi[(size_t)r * N + c] = h;
                    *(uint32_t*)&Clo[(size_t)r * N + c] = l;
                    split_pack2(v2, v3, h, l);
                    *(uint32_t*)&Chi[(size_t)(r + 8) * N + c] = h;
                    *(uint32_t*)&Clo[(size_t)(r + 8) * N + c] = l;
                }
            }
        }
    }
}

// ---------------------------------------------------------------------------
// Tensor-core flash attention, plain bf16 QK^T + PV, 3-stage KV pipeline,
// exp2 softmax. Grid (T/128, H, N), 256 threads, 2 CTAs/SM.
// ---------------------------------------------------------------------------
#define ATT_SROW 144
#define ATT_KBUF 18432          // per buf: K 9216 | V 9216
#define ATT_SMEM 55296          // 3 buffers

__global__ __launch_bounds__(256, 2)
void attention_mma_kernel(const __nv_bfloat16* __restrict__ Qb,
                          const __nv_bfloat16* __restrict__ Kb,
                          const __nv_bfloat16* __restrict__ Vb,
                          float* __restrict__ ctx)
{
    extern __shared__ char smem[];
    const uint32_t sb = (uint32_t)__cvta_generic_to_shared(smem);

    const int tid  = threadIdx.x;
    const int warp = tid >> 5;
    const int lane = tid & 31;
    const int tg   = lane & 3;
    const int grp  = lane >> 2;
    const int wm   = warp * 16;
    const int rr   = lane & 15;
    const int kb   = (lane >> 4) << 4;

    const int q0 = blockIdx.x * 128;
    const int h  = blockIdx.y;
    const int n  = blockIdx.z;
    const int h64 = h * HD;
    const size_t row_base = (size_t)n * T_SEQ;

    #pragma unroll
    for (int t = 0; t < 4; t++) {
        int u = tid + t * 256;          // 0..1023
        int row = u >> 3, ch = u & 7;
        size_t g = (size_t)(row_base + q0 + row) * DM + h64 + ch * 8;
        cp16(sb + row * ATT_SROW + ch * 16, Qb + g);
    }
    asm volatile("cp.async.commit_group;");
    asm volatile("cp.async.wait_group 0;");
    __syncthreads();

    uint32_t qf[4][4];
    #pragma unroll
    for (int kc = 0; kc < 4; kc++) {
        uint32_t ad = sb + (wm + rr) * ATT_SROW + kc * 32 + kb;
        LDSM_X4(qf[kc], ad);
    }
    __syncthreads();   // Q consumed before KV buffers overwrite the region

    auto issueKV = [&](int kt, int buf) {
        uint32_t bo = sb + buf * ATT_KBUF;
        int kv0 = kt * 64;
        #pragma unroll
        for (int t = 0; t < 2; t++) {
            int u = tid + t * 256;      // 0..511
            int row = u >> 3, ch = u & 7;
            size_t g = (size_t)(row_base + kv0 + row) * DM + h64 + ch * 8;
            uint32_t so = row * ATT_SROW + ch * 16;
            cp16(bo + so,        Kb + g);
            cp16(bo + 9216 + so, Vb + g);
        }
    };

    float o[8][4];
    #pragma unroll
    for (int j = 0; j < 8; j++)
        #pragma unroll
        for (int q = 0; q < 4; q++) o[j][q] = 0.0f;
    float m0 = -1e30f, m1 = -1e30f, l0 = 0.0f, l1 = 0.0f;

    const int nTiles = T_SEQ / 64;
    issueKV(0, 0);
    asm volatile("cp.async.commit_group;");
    issueKV(1, 1);
    asm volatile("cp.async.commit_group;");

    for (int kt = 0; kt < nTiles; kt++) {
        const int buf = kt % 3;
        asm volatile("cp.async.wait_group 1;");
        __syncthreads();
        if (kt + 2 < nTiles) {
            issueKV(kt + 2, (kt + 2) % 3);
            asm volatile("cp.async.commit_group;");
        }

        const uint32_t bo = sb + buf * ATT_KBUF;

        // ---- S = Q @ K^T (log2-domain logits), plain bf16 ----
        float s[8][4];
        #pragma unroll
        for (int j = 0; j < 8; j++)
            #pragma unroll
            for (int q = 0; q < 4; q++) s[j][q] = 0.0f;
        #pragma unroll
        for (int jj = 0; jj < 4; jj++) {
            #pragma unroll
            for (int kc = 0; kc < 4; kc++) {
                uint32_t ad = bo + (jj * 16 + rr) * ATT_SROW + kc * 32 + kb;
                uint32_t bh[4];
                LDSM_X4(bh, ad);
                uint32_t bh0[2] = { bh[0], bh[2] }, bh1[2] = { bh[1], bh[3] };
                MMA_BF16(s[2*jj],   qf[kc], bh0);
                MMA_BF16(s[2*jj+1], qf[kc], bh1);
            }
        }

        // ---- online softmax (base-2) ----
        float mx0 = -1e30f, mx1 = -1e30f;
        #pragma unroll
        for (int j = 0; j < 8; j++) {
            mx0 = fmaxf(mx0, fmaxf(s[j][0], s[j][1]));
            mx1 = fmaxf(mx1, fmaxf(s[j][2], s[j][3]));
        }
        mx0 = fmaxf(mx0, __shfl_xor_sync(0xffffffff, mx0, 1));
        mx0 = fmaxf(mx0, __shfl_xor_sync(0xffffffff, mx0, 2));
        mx1 = fmaxf(mx1, __shfl_xor_sync(0xffffffff, mx1, 1));
        mx1 = fmaxf(mx1, __shfl_xor_sync(0xffffffff, mx1, 2));
        float mn0 = fmaxf(m0, mx0), mn1 = fmaxf(m1, mx1);
        float al0 = exp2f(m0 - mn0), al1 = exp2f(m1 - mn1);
        float sum0 = 0.0f, sum1 = 0.0f;
        #pragma unroll
        for (int j = 0; j < 8; j++) {
            s[j][0] = exp2f(s[j][0] - mn0);
            s[j][1] = exp2f(s[j][1] - mn0);
            s[j][2] = exp2f(s[j][2] - mn1);
            s[j][3] = exp2f(s[j][3] - mn1);
            sum0 += s[j][0] + s[j][1];
            sum1 += s[j][2] + s[j][3];
        }
        sum0 += __shfl_xor_sync(0xffffffff, sum0, 1);
        sum0 += __shfl_xor_sync(0xffffffff, sum0, 2);
        sum1 += __shfl_xor_sync(0xffffffff, sum1, 1);
        sum1 += __shfl_xor_sync(0xffffffff, sum1, 2);
        m0 = mn0; m1 = mn1;
        l0 = l0 * al0 + sum0;
        l1 = l1 * al1 + sum1;
        #pragma unroll
        for (int j = 0; j < 8; j++) {
            o[j][0] *= al0; o[j][1] *= al0;
            o[j][2] *= al1; o[j][3] *= al1;
        }

        // ---- P fragments + PV (V via ldmatrix.trans) ----
        uint32_t ap[4][4];
        #pragma unroll
        for (int kc = 0; kc < 4; kc++) {
            ap[kc][0] = pack_bf16(s[2*kc][0],   s[2*kc][1]);
            ap[kc][1] = pack_bf16(s[2*kc][2],   s[2*kc][3]);
            ap[kc][2] = pack_bf16(s[2*kc+1][0], s[2*kc+1][1]);
            ap[kc][3] = pack_bf16(s[2*kc+1][2], s[2*kc+1][3]);
        }
        const uint32_t vrow = ((lane >> 4) << 3) + (lane & 7);
        const uint32_t vcol = ((lane >> 3) & 1) << 3;
        #pragma unroll
        for (int jd = 0; jd < 4; jd++) {
            #pragma unroll
            for (int kc = 0; kc < 4; kc++) {
                uint32_t va = bo + 9216 + (kc * 16 + vrow) * ATT_SROW
                            + (jd * 16 + vcol) * 2;
                uint32_t vr[4];
                LDSM_X4_T(vr, va);
                uint32_t vg0[2] = { vr[0], vr[2] }, vg1[2] = { vr[1], vr[3] };
                MMA_BF16(o[2*jd],   ap[kc], vg0);
                MMA_BF16(o[2*jd+1], ap[kc], vg1);
            }
        }
    }

    // ---- epilogue ----
    float inv0 = 1.0f / l0, inv1 = 1.0f / l1;
    size_t r0 = (row_base + q0 + wm + grp) * (size_t)DM + h64;
    size_t r1 = r0 + 8 * (size_t)DM;
    #pragma unroll
    for (int j = 0; j < 8; j++) {
        int c = j * 8 + tg * 2;
        *(float2*)&ctx[r0 + c] = make_float2(o[j][0] * inv0, o[j][1] * inv0);
        *(float2*)&ctx[r1 + c] = make_float2(o[j][2] * inv1, o[j][3] * inv1);
    }
}

// ---------------------------------------------------------------------------
// out = LayerNorm(a + b) * gamma + beta; optional hi/lo bf16 side outputs.
// ---------------------------------------------------------------------------
__global__ void add_ln_kernel(const float* __restrict__ a,
                              const float* __restrict__ b,
                              const float* __restrict__ gamma,
                              const float* __restrict__ beta,
                              float* __restrict__ out,
                              __nv_bfloat16* __restrict__ ohi,
                              __nv_bfloat16* __restrict__ olo)
{
    __shared__ float red[256];
    const int row = blockIdx.x;
    const int tid = threadIdx.x;
    const size_t base = (size_t)row * DM;

    float v[4];
    float s = 0.0f;
    #pragma unroll
    for (int i = 0; i < 4; i++) {
        int c = tid + 256 * i;
        v[i] = a[base + c] + b[base + c];
        s += v[i];
    }
    red[tid] = s;
    __syncthreads();
    #pragma unroll
    for (int off = 128; off > 0; off >>= 1) {
        if (tid < off) red[tid] += red[tid + off];
        __syncthreads();
    }
    const float mu = red[0] * (1.0f / DM);
    __syncthreads();

    float s2 = 0.0f;
    #pragma unroll
    for (int i = 0; i < 4; i++) {
        float d = v[i] - mu;
        s2 += d * d;
    }
    red[tid] = s2;
    __syncthreads();
    #pragma unroll
    for (int off = 128; off > 0; off >>= 1) {
        if (tid < off) red[tid] += red[tid + off];
        __syncthreads();
    }
    const float rs = rsqrtf(red[0] * (1.0f / DM) + LN_EPS);

    #pragma unroll
    for (int i = 0; i < 4; i++) {
        int c = tid + 256 * i;
        float y = (v[i] - mu) * rs * gamma[c] + beta[c];
        out[base + c] = y;
        if (ohi) {
            __nv_bfloat16 hb = __float2bfloat16(y);
            ohi[base + c] = hb;
            olo[base + c] = __float2bfloat16(y - __bfloat162float(hb));
        }
    }
}

// ---------------------------------------------------------------------------
// Launch
// ---------------------------------------------------------------------------
extern "C" void kernel_launch(void* const* d_in, const int* in_sizes, int n_in,
                              void* d_out, int out_size)
{
    const float* x     = (const float*)d_in[0];
    /* mask = d_in[1] : query-axis mask -> softmax shift -> no-op */
    const float* w_qkv = (const float*)d_in[2];
    const float* b_qkv = (const float*)d_in[3];
    const float* w_ff  = (const float*)d_in[4];
    const float* b_ff  = (const float*)d_in[5];
    const float* w_out = (const float*)d_in[6];
    const float* b_out = (const float*)d_in[7];
    const float* ln1_g = (const float*)d_in[8];
    const float* ln1_b = (const float*)d_in[9];
    const float* ln2_g = (const float*)d_in[10];
    const float* ln2_b = (const float*)d_in[11];
    float* out = (float*)d_out;

    float *ctx, *h1, *tmp;
    __nv_bfloat16 *ahi, *alo, *bhi, *blo, *ffhi, *fflo;
    __nv_bfloat16 *qb, *kb, *vb;
    cudaGetSymbolAddress((void**)&ctx,  g_ctx);
    cudaGetSymbolAddress((void**)&h1,   g_h1);
    cudaGetSymbolAddress((void**)&tmp,  g_tmp);
    cudaGetSymbolAddress((void**)&ahi,  g_ahi);
    cudaGetSymbolAddress((void**)&alo,  g_alo);
    cudaGetSymbolAddress((void**)&bhi,  g_bhi);
    cudaGetSymbolAddress((void**)&blo,  g_blo);
    cudaGetSymbolAddress((void**)&ffhi, g_ffhi);
    cudaGetSymbolAddress((void**)&fflo, g_fflo);
    cudaGetSymbolAddress((void**)&qb,   g_qb);
    cudaGetSymbolAddress((void**)&kb,   g_kb);
    cudaGetSymbolAddress((void**)&vb,   g_vb);

    static int smem_set = 0;
    if (!smem_set) {
        cudaFuncSetAttribute(gemm_mma_kernel<1>,
                             cudaFuncAttributeMaxDynamicSharedMemorySize,
                             GEMM_SMEM_BYTES);
        cudaFuncSetAttribute(gemm_mma_kernel<0>,
                             cudaFuncAttributeMaxDynamicSharedMemorySize,
                             GEMM_SMEM_PLAIN);
        cudaFuncSetAttribute(attention_mma_kernel,
                             cudaFuncAttributeMaxDynamicSharedMemorySize,
                             ATT_SMEM);
        smem_set = 1;
    }

    // 0) Convert x -> hi/lo; w_qkv -> transposed+permuted hi only
    convert_split_kernel<<<(NT * DM / 2 + 255) / 256, 256>>>(x, ahi, alo, NT * DM / 2);
    convert_wT_kernel<<<dim3(QKV_N / 32, DM / 32), dim3(32, 8)>>>(
        w_qkv, bhi, blo, DM, QKV_N, 1, 0);

    // 1) QKV projection (plain bf16 — outputs are bf16 anyway)
    gemm_mma_kernel<0><<<dim3(QKV_N / 128, NT / 128), 256, GEMM_SMEM_PLAIN>>>(
        ahi, alo, bhi, blo, b_qkv, nullptr, nullptr, nullptr,
        qb, kb, vb, QKV_N, DM, 0);

    // 2) Attention
    attention_mma_kernel<<<dim3(T_SEQ / 128, H_NUM, NB), 256, ATT_SMEM>>>(
        qb, kb, vb, ctx);

    // 3) h1 = LN(x + ctx), emit h1 hi/lo
    add_ln_kernel<<<NT, 256>>>(x, ctx, ln1_g, ln1_b, h1, ahi, alo);

    // 4) ff = relu(h1 @ w_ff + b_ff) -> hi/lo bf16  (full split precision)
    convert_wT_kernel<<<dim3(DFF / 32, DM / 32), dim3(32, 8)>>>(
        w_ff, bhi, blo, DM, DFF, 0, 1);
    gemm_mma_kernel<1><<<dim3(DFF / 128, NT / 128), 256, GEMM_SMEM_BYTES>>>(
        ahi, alo, bhi, blo, b_ff, nullptr, ffhi, fflo,
        nullptr, nullptr, nullptr, DFF, DM, 1);

    // 5) tmp = ff @ w_out + b_out -> fp32  (full split precision)
    convert_wT_kernel<<<dim3(DM / 32, DFF / 32), dim3(32, 8)>>>(
        w_out, bhi, blo, DFF, DM, 0, 1);
    gemm_mma_kernel<1><<<dim3(DM / 128, NT / 128), 256, GEMM_SMEM_BYTES>>>(
        ffhi, fflo, bhi, blo, b_out, tmp, nullptr, nullptr,
        nullptr, nullptr, nullptr, DM, DFF, 0);

    // 6) out = LN(h1 + tmp)
    add_ln_kernel<<<NT, 256>>>(h1, tmp, ln2_g, ln2_b, out, nullptr, nullptr);
}